// round 10
// baseline (speedup 1.0000x reference)
#include <cuda_runtime.h>
#include <cuda_bf16.h>
#include <math.h>
#include <stdint.h>

#define T_STEPS 1024
#define BATCH   64
#define IDIM    512
#define HDIM    512
#define G4      2048   // 4*H
#define MTOT    (T_STEPS * BATCH)   // 65536

// ---- device-global scratch (no allocs allowed) ----
__device__ float        g_xproj[(size_t)MTOT * G4];   // 512 MB
__device__ uint32_t     g_hpack[BATCH * HDIM];        // packed bf16 hi|lo of h
__device__ unsigned int g_bar4[4 * 32];               // per-batch-group flags
__device__ unsigned int g_done;

__device__ __forceinline__ float sigf(float x) {
    return __fdividef(1.0f, 1.0f + __expf(-x));
}

// ---------------- mma.sync helpers (baseline PTX, no 'a' features) ----------
__device__ __forceinline__ uint32_t smem_u32(const void* p) {
    uint32_t a;
    asm("{ .reg .u64 t; cvta.to.shared.u64 t, %1; cvt.u32.u64 %0, t; }"
        : "=r"(a) : "l"(p));
    return a;
}
__device__ __forceinline__ uint32_t prmt(uint32_t a, uint32_t b, uint32_t s) {
    uint32_t r;
    asm("prmt.b32 %0, %1, %2, %3;" : "=r"(r) : "r"(a), "r"(b), "r"(s));
    return r;
}
__device__ __forceinline__ void ldm4(uint32_t* r, uint32_t addr) {
    asm volatile("ldmatrix.sync.aligned.m8n8.x4.shared.b16 {%0,%1,%2,%3}, [%4];"
                 : "=r"(r[0]), "=r"(r[1]), "=r"(r[2]), "=r"(r[3]) : "r"(addr));
}
__device__ __forceinline__ void mma16816(float* d, const uint32_t* a,
                                         uint32_t b0, uint32_t b1) {
    asm volatile(
        "mma.sync.aligned.m16n8k16.row.col.f32.bf16.bf16.f32 "
        "{%0,%1,%2,%3}, {%4,%5,%6,%7}, {%8,%9}, {%0,%1,%2,%3};"
        : "+f"(d[0]), "+f"(d[1]), "+f"(d[2]), "+f"(d[3])
        : "r"(a[0]), "r"(a[1]), "r"(a[2]), "r"(a[3]), "r"(b0), "r"(b1));
}
// split one fp32x4 into packed bf16 hi-pair / lo-pair words
__device__ __forceinline__ void split4(const float4 v, uint2& hi, uint2& lo) {
    __nv_bfloat16 h0 = __float2bfloat16(v.x), h1 = __float2bfloat16(v.y);
    __nv_bfloat16 h2 = __float2bfloat16(v.z), h3 = __float2bfloat16(v.w);
    __nv_bfloat16 l0 = __float2bfloat16(v.x - __bfloat162float(h0));
    __nv_bfloat16 l1 = __float2bfloat16(v.y - __bfloat162float(h1));
    __nv_bfloat16 l2 = __float2bfloat16(v.z - __bfloat162float(h2));
    __nv_bfloat16 l3 = __float2bfloat16(v.w - __bfloat162float(h3));
    hi.x = (uint32_t)__bfloat16_as_ushort(h0) |
           ((uint32_t)__bfloat16_as_ushort(h1) << 16);
    hi.y = (uint32_t)__bfloat16_as_ushort(h2) |
           ((uint32_t)__bfloat16_as_ushort(h3) << 16);
    lo.x = (uint32_t)__bfloat16_as_ushort(l0) |
           ((uint32_t)__bfloat16_as_ushort(l1) << 16);
    lo.y = (uint32_t)__bfloat16_as_ushort(l2) |
           ((uint32_t)__bfloat16_as_ushort(l3) << 16);
}
__device__ __forceinline__ uint32_t pack_hilo(float v) {
    __nv_bfloat16 h = __float2bfloat16(v);
    __nv_bfloat16 l = __float2bfloat16(v - __bfloat162float(h));
    return (uint32_t)__bfloat16_as_ushort(h) |
           ((uint32_t)__bfloat16_as_ushort(l) << 16);
}

// ---------------------------------------------------------------------------
// Kernel 1: x_proj via bf16 hi/lo-split HMMA (UNCHANGED, passing)
// ---------------------------------------------------------------------------
#define XS_ROW   80
#define XS_BUF   (128 * XS_ROW)
__global__ void __launch_bounds__(256, 1) xproj_mma_kernel(
    const float* __restrict__ A, const float* __restrict__ W,
    const float* __restrict__ bih, const float* __restrict__ bhh)
{
    __shared__ __align__(16) char sAH[XS_BUF];
    __shared__ __align__(16) char sAL[XS_BUF];
    __shared__ __align__(16) char sWH[XS_BUF];
    __shared__ __align__(16) char sWL[XS_BUF];
    __shared__ float sBias[128];

    const int tid = threadIdx.x;
    const int n0 = blockIdx.x * 128;
    const int m0 = blockIdx.y * 128;
    const int lane = tid & 31, wid = tid >> 5;
    const int wm = wid >> 1, wn = wid & 1;

    if (tid < 128) sBias[tid] = bih[n0 + tid] + bhh[n0 + tid];

    const int srow = tid >> 3;
    const int sc4  = (tid & 7) << 2;
    const float* agp = A + (size_t)(m0 + srow) * IDIM + sc4;
    const float* wgp = W + (size_t)(n0 + srow) * IDIM + sc4;

    const int lr = lane & 7, sel = lane >> 3;
    const int koff2 = ((sel >> 1) * 8) * 2;
    const uint32_t aH = smem_u32(sAH) + (uint32_t)(wm * 32 + (sel & 1) * 8 + lr) * XS_ROW + koff2;
    const uint32_t aL = smem_u32(sAL) + (uint32_t)(wm * 32 + (sel & 1) * 8 + lr) * XS_ROW + koff2;
    const uint32_t bH = smem_u32(sWH) + (uint32_t)(wn * 64 + (sel & 1) * 8 + lr) * XS_ROW + koff2;
    const uint32_t bL = smem_u32(sWL) + (uint32_t)(wn * 64 + (sel & 1) * 8 + lr) * XS_ROW + koff2;

    float d[2][8][4];
#pragma unroll
    for (int i = 0; i < 2; i++)
#pragma unroll
        for (int j = 0; j < 8; j++)
#pragma unroll
            for (int q = 0; q < 4; q++) d[i][j][q] = 0.0f;

    float4 pfA[4], pfW[4];
#pragma unroll
    for (int i = 0; i < 4; i++) {
        pfA[i] = *(const float4*)(agp + i * 32 * IDIM);
        pfW[i] = *(const float4*)(wgp + i * 32 * IDIM);
    }

    for (int kc = 0; kc < 16; kc++) {
#pragma unroll
        for (int i = 0; i < 4; i++) {
            int row = srow + i * 32;
            uint2 hi, lo;
            split4(pfA[i], hi, lo);
            *(uint2*)(sAH + row * XS_ROW + sc4 * 2) = hi;
            *(uint2*)(sAL + row * XS_ROW + sc4 * 2) = lo;
            split4(pfW[i], hi, lo);
            *(uint2*)(sWH + row * XS_ROW + sc4 * 2) = hi;
            *(uint2*)(sWL + row * XS_ROW + sc4 * 2) = lo;
        }
        __syncthreads();

        if (kc < 15) {
            const float* an = agp + (kc + 1) * 32;
            const float* wnp = wgp + (kc + 1) * 32;
#pragma unroll
            for (int i = 0; i < 4; i++) {
                pfA[i] = *(const float4*)(an + i * 32 * IDIM);
                pfW[i] = *(const float4*)(wnp + i * 32 * IDIM);
            }
        }

#pragma unroll
        for (int k16 = 0; k16 < 2; k16++) {
            const uint32_t ko = (uint32_t)(k16 * 32);
            uint32_t ah[2][4], al[2][4];
            ldm4(ah[0], aH + ko);
            ldm4(ah[1], aH + ko + 16 * XS_ROW);
            ldm4(al[0], aL + ko);
            ldm4(al[1], aL + ko + 16 * XS_ROW);
#pragma unroll
            for (int bnp = 0; bnp < 4; bnp++) {
                uint32_t bh[4], bl[4];
                ldm4(bh, bH + ko + (uint32_t)(bnp * 16) * XS_ROW);
                mma16816(d[0][2 * bnp],     ah[0], bh[0], bh[2]);
                mma16816(d[0][2 * bnp + 1], ah[0], bh[1], bh[3]);
                mma16816(d[1][2 * bnp],     ah[1], bh[0], bh[2]);
                mma16816(d[1][2 * bnp + 1], ah[1], bh[1], bh[3]);
                mma16816(d[0][2 * bnp],     al[0], bh[0], bh[2]);
                mma16816(d[0][2 * bnp + 1], al[0], bh[1], bh[3]);
                mma16816(d[1][2 * bnp],     al[1], bh[0], bh[2]);
                mma16816(d[1][2 * bnp + 1], al[1], bh[1], bh[3]);
                ldm4(bl, bL + ko + (uint32_t)(bnp * 16) * XS_ROW);
                mma16816(d[0][2 * bnp],     ah[0], bl[0], bl[2]);
                mma16816(d[0][2 * bnp + 1], ah[0], bl[1], bl[3]);
                mma16816(d[1][2 * bnp],     ah[1], bl[0], bl[2]);
                mma16816(d[1][2 * bnp + 1], ah[1], bl[1], bl[3]);
            }
        }
        __syncthreads();
    }

    const int erow = m0 + wm * 32 + (lane >> 2);
    const int ecol = wn * 64 + (lane & 3) * 2;
#pragma unroll
    for (int am = 0; am < 2; am++) {
#pragma unroll
        for (int bn = 0; bn < 8; bn++) {
            int col = ecol + bn * 8;
            float b0 = sBias[col], b1 = sBias[col + 1];
            float* p0 = g_xproj + (size_t)(erow + am * 16) * G4 + n0 + col;
            float* p1 = p0 + 8 * G4;
            *(float2*)p0 = make_float2(d[am][bn][0] + b0, d[am][bn][1] + b1);
            *(float2*)p1 = make_float2(d[am][bn][2] + b0, d[am][bn][3] + b1);
        }
    }
}

// ---------------------------------------------------------------------------
// Kernel 2: recurrence. h0 packing folded in (pre-loop, own block + release);
// stage path uniform from g_hpack; xp prefetched one full step ahead.
// W fragments in registers; warp-15 poll; per-warp early release;
// partials [kw][b*68+cc] (plane stride 1092).
// ---------------------------------------------------------------------------
#define OFF_WHI  0                         // 64 rows x 1040 B
#define OFF_WLO  66560
#define OFF_HHI  133120                    // 16 rows x 1040 B
#define OFF_HLO  149760
#define OFF_XP   166400                    // float [16][64]
#define OFF_P9   170496                    // float [8][1092]  (34944 B)
#define OFF_C    205440                    // float [256]
#define R_SMEM   206464

__global__ void __launch_bounds__(512, 1) recur_mma_kernel(
    const float* __restrict__ h0, const float* __restrict__ c0,
    const float* __restrict__ Whh, float* __restrict__ out)
{
    extern __shared__ char sm[];
    float* xp_s = (float*)(sm + OFF_XP);
    float* p9   = (float*)(sm + OFF_P9);
    float* c_s  = (float*)(sm + OFF_C);

    const int tid  = threadIdx.x;
    const int lane = tid & 31, wid = tid >> 5;
    const int kw = wid >> 1;               // K slice of 64 (0..7)
    const int nw = wid & 1;                // n slice of 32 (0..1)
    const int j0 = blockIdx.x * 16;
    const int B0 = blockIdx.y * 16;
    const int grp = blockIdx.y;
    unsigned int* flag = &g_bar4[grp * 32];

    // ---- convert W_hh slice to bf16 hi/lo in SMEM (once) ----
#pragma unroll 4
    for (int i = 0; i < 16; i++) {
        int idx = tid + i * 512;
        int row = idx >> 7;                // 0..63 (gate*16+jj)
        int f4  = (idx & 127) << 2;
        int gate = row >> 4, jj = row & 15;
        float4 v = *(const float4*)(Whh
                      + (size_t)(gate * HDIM + j0 + jj) * HDIM + f4);
        uint2 hi, lo;
        split4(v, hi, lo);
        *(uint2*)(sm + OFF_WHI + row * 1040 + f4 * 2) = hi;
        *(uint2*)(sm + OFF_WLO + row * 1040 + f4 * 2) = lo;
    }
    // ---- pack own h0 block into g_hpack + initial release (unit: 8/CTA) ----
    if (tid < 256) {
        int b = tid >> 4, jj = tid & 15;
        c_s[tid] = c0[(size_t)(B0 + b) * HDIM + j0 + jj];
        float hv = h0[(size_t)(B0 + b) * HDIM + j0 + jj];
        g_hpack[(B0 + b) * HDIM + j0 + jj] = pack_hilo(hv);
        __syncwarp();
        if (lane == 0) {
            asm volatile("red.release.gpu.global.add.u32 [%0], %1;"
                         :: "l"(flag), "r"(1u) : "memory");
        }
    }
    __syncthreads();

    // ---- load B (W) fragments into registers (once) ----
    const int lr = lane & 7, sel = lane >> 3;
    uint32_t BH[4][2][4], BL[4][2][4];
#pragma unroll
    for (int ks = 0; ks < 4; ks++)
#pragma unroll
        for (int p = 0; p < 2; p++) {
            uint32_t off = (uint32_t)(nw * 32 + p * 16 + (sel & 1) * 8 + lr) * 1040u
                         + (uint32_t)((sel >> 1) * 16)
                         + (uint32_t)(kw * 128 + ks * 32);
            ldm4(BH[ks][p], smem_u32(sm + OFF_WHI) + off);
            ldm4(BL[ks][p], smem_u32(sm + OFF_WLO) + off);
        }

    // ---- A (h) ldmatrix addressing ----
    const uint32_t aRowOff = (uint32_t)((sel & 1) * 8 + lr) * 1040u
                           + (uint32_t)((sel >> 1) * 16)
                           + (uint32_t)(kw * 128);
    const uint32_t aHiB = smem_u32(sm + OFF_HHI) + aRowOff;
    const uint32_t aLoB = smem_u32(sm + OFF_HLO) + aRowOff;

    // staging map: thread -> row r (batch), 16 packed u32 cols at cb
    const int sr  = tid & 15;
    const int scb = (tid >> 4) * 16;
    const uint4* hgp = (const uint4*)(g_hpack + (B0 + sr) * HDIM + scb);
    char* dH = sm + OFF_HHI + sr * 1040 + scb * 2;
    char* dL = sm + OFF_HLO + sr * 1040 + scb * 2;

    // xp prefetch state (one full step ahead)
    const int xb = tid >> 4, xq = tid & 15;
    const int xg = xq >> 2, xf = xq & 3;
    float4 xv;
    if (tid < 256) {
        xv = *(const float4*)(g_xproj
                + ((size_t)(T_STEPS - 1) * BATCH + B0 + xb) * G4
                + xg * HDIM + j0 + xf * 4);
    }

    for (int t = T_STEPS - 1; t >= 0; t--) {
        // ---- warp 15 polls; everyone gates on syncthreads ----
        if (wid == 15) {
            unsigned target = (unsigned)(T_STEPS - t) * 256u;
            unsigned v;
            do {
                asm volatile("ld.acquire.gpu.global.u32 %0, [%1];"
                             : "=r"(v) : "l"(flag) : "memory");
            } while (v < target);
        }
        __syncthreads();

        // ---- stage h: unpack packed hi|lo with prmt; store prefetched xp ----
        {
            uint4 p0 = hgp[0], p1 = hgp[1], p2 = hgp[2], p3 = hgp[3];
            uint2 h_, l_;
            h_.x = prmt(p0.x, p0.y, 0x5410); l_.x = prmt(p0.x, p0.y, 0x7632);
            h_.y = prmt(p0.z, p0.w, 0x5410); l_.y = prmt(p0.z, p0.w, 0x7632);
            *(uint2*)(dH +  0) = h_; *(uint2*)(dL +  0) = l_;
            h_.x = prmt(p1.x, p1.y, 0x5410); l_.x = prmt(p1.x, p1.y, 0x7632);
            h_.y = prmt(p1.z, p1.w, 0x5410); l_.y = prmt(p1.z, p1.w, 0x7632);
            *(uint2*)(dH +  8) = h_; *(uint2*)(dL +  8) = l_;
            h_.x = prmt(p2.x, p2.y, 0x5410); l_.x = prmt(p2.x, p2.y, 0x7632);
            h_.y = prmt(p2.z, p2.w, 0x5410); l_.y = prmt(p2.z, p2.w, 0x7632);
            *(uint2*)(dH + 16) = h_; *(uint2*)(dL + 16) = l_;
            h_.x = prmt(p3.x, p3.y, 0x5410); l_.x = prmt(p3.x, p3.y, 0x7632);
            h_.y = prmt(p3.z, p3.w, 0x5410); l_.y = prmt(p3.z, p3.w, 0x7632);
            *(uint2*)(dH + 24) = h_; *(uint2*)(dL + 24) = l_;
            if (tid < 256)
                *(float4*)(xp_s + xb * 64 + xg * 16 + xf * 4) = xv;
        }
        __syncthreads();

        // ---- prefetch NEXT step's xp (hides DRAM latency fully) ----
        if (t > 0 && tid < 256) {
            xv = *(const float4*)(g_xproj
                    + ((size_t)(t - 1) * BATCH + B0 + xb) * G4
                    + xg * HDIM + j0 + xf * 4);
        }

        // ---- MMA: 4 k16 steps, B from registers ----
        float acc[4][4];
#pragma unroll
        for (int q = 0; q < 4; q++)
#pragma unroll
            for (int i = 0; i < 4; i++) acc[q][i] = 0.0f;
#pragma unroll
        for (int ks = 0; ks < 4; ks++) {
            uint32_t ah[4], al[4];
            ldm4(ah, aHiB + (uint32_t)(ks * 32));
            ldm4(al, aLoB + (uint32_t)(ks * 32));
#pragma unroll
            for (int q = 0; q < 4; q++) {
                const int p = q >> 1, hh = q & 1;
                mma16816(acc[q], ah, BH[ks][p][hh], BH[ks][p][hh + 2]);
                mma16816(acc[q], al, BH[ks][p][hh], BH[ks][p][hh + 2]);
                mma16816(acc[q], ah, BL[ks][p][hh], BL[ks][p][hh + 2]);
            }
        }
        // ---- store partials: p9[kw][b*68 + cc], STS.64 ----
        {
            const int r = lane >> 2;
            const int c2 = (lane & 3) * 2;
            float* base = p9 + kw * 1092;
#pragma unroll
            for (int q = 0; q < 4; q++) {
                int cc = nw * 32 + q * 8 + c2;
                *(float2*)(base + r * 68 + cc)       = make_float2(acc[q][0], acc[q][1]);
                *(float2*)(base + (r + 8) * 68 + cc) = make_float2(acc[q][2], acc[q][3]);
            }
        }
        __syncthreads();

        // ---- reduce 8 K-slices + cell update (256 threads), early release ----
        if (tid < 256) {
            int b = tid >> 4, jj = tid & 15;
            float pre[4];
#pragma unroll
            for (int g = 0; g < 4; g++) {
                int off = b * 68 + g * 16 + jj;
                float s0 = p9[off]            + p9[1092 + off];
                float s1 = p9[2 * 1092 + off] + p9[3 * 1092 + off];
                float s2 = p9[4 * 1092 + off] + p9[5 * 1092 + off];
                float s3 = p9[6 * 1092 + off] + p9[7 * 1092 + off];
                pre[g] = ((s0 + s1) + (s2 + s3)) + xp_s[b * 64 + g * 16 + jj];
            }
            float gi = sigf(pre[0]);
            float gf = sigf(pre[1]);
            float gz = sigf(pre[2]);
            float go = sigf(pre[3]);
            float cn = gf * c_s[tid] + gz - gi;
            c_s[tid] = cn;
            float hn = sigf(cn) - go;
            out[(size_t)t * (BATCH * HDIM) + (size_t)(B0 + b) * HDIM + j0 + jj] = hn;
            g_hpack[(B0 + b) * HDIM + j0 + jj] = pack_hilo(hn);
            if (t == 0) {
                const size_t base = (size_t)T_STEPS * BATCH * HDIM;
                out[base + (size_t)(B0 + b) * HDIM + j0 + jj] = hn;
                out[base + BATCH * HDIM + (size_t)(B0 + b) * HDIM + j0 + jj] = cn;
            }
            __syncwarp();
            if (lane == 0 && t > 0) {
                asm volatile("red.release.gpu.global.add.u32 [%0], %1;"
                             :: "l"(flag), "r"(1u) : "memory");
            }
        }
    }

    // ---- self-reset of counters (after ALL 128 CTAs finish) ----
    __syncthreads();
    if (tid == 0) {
        unsigned v = atomicAdd(&g_done, 1u);
        if (v == 127u) {
            atomicExch(&g_bar4[0], 0u);
            atomicExch(&g_bar4[32], 0u);
            atomicExch(&g_bar4[64], 0u);
            atomicExch(&g_bar4[96], 0u);
            atomicExch(&g_done, 0u);
        }
    }
}

// ---------------------------------------------------------------------------
extern "C" void kernel_launch(void* const* d_in, const int* in_sizes, int n_in,
                              void* d_out, int out_size)
{
    const float* input = (const float*)d_in[0];
    const float* h0    = (const float*)d_in[1];
    const float* c0    = (const float*)d_in[2];
    const float* Wih   = (const float*)d_in[3];
    const float* Whh   = (const float*)d_in[4];
    const float* bih   = (const float*)d_in[5];
    const float* bhh   = (const float*)d_in[6];
    float* out = (float*)d_out;

    static int configured = 0;
    if (!configured) {
        cudaFuncSetAttribute(recur_mma_kernel,
                             cudaFuncAttributeMaxDynamicSharedMemorySize,
                             R_SMEM);
        configured = 1;
    }

    xproj_mma_kernel<<<dim3(G4 / 128, MTOT / 128), 256>>>(input, Wih, bih, bhh);
    recur_mma_kernel<<<dim3(HDIM / 16, BATCH / 16), 512, R_SMEM>>>(
        h0, c0, Whh, out);
}

// round 11
// speedup vs baseline: 1.2019x; 1.2019x over previous
#include <cuda_runtime.h>
#include <cuda_bf16.h>
#include <math.h>
#include <stdint.h>

#define T_STEPS 1024
#define BATCH   64
#define IDIM    512
#define HDIM    512
#define G4      2048   // 4*H
#define MTOT    (T_STEPS * BATCH)   // 65536
#define BHD     (BATCH * HDIM)

// ---- device-global scratch (no allocs allowed) ----
__device__ float        g_xproj[(size_t)MTOT * G4];   // 512 MB
__device__ uint32_t     g_hpack[2 * BHD];             // double-buffered packed h
__device__ unsigned int g_barF[4 * 8 * 32];           // per-(group, K-slice) flags
__device__ unsigned int g_done;

__device__ __forceinline__ float sigf(float x) {
    return __fdividef(1.0f, 1.0f + __expf(-x));
}

// ---------------- helpers ----------------
__device__ __forceinline__ uint32_t smem_u32(const void* p) {
    uint32_t a;
    asm("{ .reg .u64 t; cvta.to.shared.u64 t, %1; cvt.u32.u64 %0, t; }"
        : "=r"(a) : "l"(p));
    return a;
}
__device__ __forceinline__ uint32_t prmt(uint32_t a, uint32_t b, uint32_t s) {
    uint32_t r;
    asm("prmt.b32 %0, %1, %2, %3;" : "=r"(r) : "r"(a), "r"(b), "r"(s));
    return r;
}
__device__ __forceinline__ void ldm4(uint32_t* r, uint32_t addr) {
    asm volatile("ldmatrix.sync.aligned.m8n8.x4.shared.b16 {%0,%1,%2,%3}, [%4];"
                 : "=r"(r[0]), "=r"(r[1]), "=r"(r[2]), "=r"(r[3]) : "r"(addr));
}
__device__ __forceinline__ void mma16816(float* d, const uint32_t* a,
                                         uint32_t b0, uint32_t b1) {
    asm volatile(
        "mma.sync.aligned.m16n8k16.row.col.f32.bf16.bf16.f32 "
        "{%0,%1,%2,%3}, {%4,%5,%6,%7}, {%8,%9}, {%0,%1,%2,%3};"
        : "+f"(d[0]), "+f"(d[1]), "+f"(d[2]), "+f"(d[3])
        : "r"(a[0]), "r"(a[1]), "r"(a[2]), "r"(a[3]), "r"(b0), "r"(b1));
}
__device__ __forceinline__ void split4(const float4 v, uint2& hi, uint2& lo) {
    __nv_bfloat16 h0 = __float2bfloat16(v.x), h1 = __float2bfloat16(v.y);
    __nv_bfloat16 h2 = __float2bfloat16(v.z), h3 = __float2bfloat16(v.w);
    __nv_bfloat16 l0 = __float2bfloat16(v.x - __bfloat162float(h0));
    __nv_bfloat16 l1 = __float2bfloat16(v.y - __bfloat162float(h1));
    __nv_bfloat16 l2 = __float2bfloat16(v.z - __bfloat162float(h2));
    __nv_bfloat16 l3 = __float2bfloat16(v.w - __bfloat162float(h3));
    hi.x = (uint32_t)__bfloat16_as_ushort(h0) |
           ((uint32_t)__bfloat16_as_ushort(h1) << 16);
    hi.y = (uint32_t)__bfloat16_as_ushort(h2) |
           ((uint32_t)__bfloat16_as_ushort(h3) << 16);
    lo.x = (uint32_t)__bfloat16_as_ushort(l0) |
           ((uint32_t)__bfloat16_as_ushort(l1) << 16);
    lo.y = (uint32_t)__bfloat16_as_ushort(l2) |
           ((uint32_t)__bfloat16_as_ushort(l3) << 16);
}
__device__ __forceinline__ uint32_t pack_hilo(float v) {
    __nv_bfloat16 h = __float2bfloat16(v);
    __nv_bfloat16 l = __float2bfloat16(v - __bfloat162float(h));
    return (uint32_t)__bfloat16_as_ushort(h) |
           ((uint32_t)__bfloat16_as_ushort(l) << 16);
}

// ---------------------------------------------------------------------------
// Kernel 1: x_proj via bf16 hi/lo-split HMMA (UNCHANGED, passing)
// ---------------------------------------------------------------------------
#define XS_ROW   80
#define XS_BUF   (128 * XS_ROW)
__global__ void __launch_bounds__(256, 1) xproj_mma_kernel(
    const float* __restrict__ A, const float* __restrict__ W,
    const float* __restrict__ bih, const float* __restrict__ bhh)
{
    __shared__ __align__(16) char sAH[XS_BUF];
    __shared__ __align__(16) char sAL[XS_BUF];
    __shared__ __align__(16) char sWH[XS_BUF];
    __shared__ __align__(16) char sWL[XS_BUF];
    __shared__ float sBias[128];

    const int tid = threadIdx.x;
    const int n0 = blockIdx.x * 128;
    const int m0 = blockIdx.y * 128;
    const int lane = tid & 31, wid = tid >> 5;
    const int wm = wid >> 1, wn = wid & 1;

    if (tid < 128) sBias[tid] = bih[n0 + tid] + bhh[n0 + tid];

    const int srow = tid >> 3;
    const int sc4  = (tid & 7) << 2;
    const float* agp = A + (size_t)(m0 + srow) * IDIM + sc4;
    const float* wgp = W + (size_t)(n0 + srow) * IDIM + sc4;

    const int lr = lane & 7, sel = lane >> 3;
    const int koff2 = ((sel >> 1) * 8) * 2;
    const uint32_t aH = smem_u32(sAH) + (uint32_t)(wm * 32 + (sel & 1) * 8 + lr) * XS_ROW + koff2;
    const uint32_t aL = smem_u32(sAL) + (uint32_t)(wm * 32 + (sel & 1) * 8 + lr) * XS_ROW + koff2;
    const uint32_t bH = smem_u32(sWH) + (uint32_t)(wn * 64 + (sel & 1) * 8 + lr) * XS_ROW + koff2;
    const uint32_t bL = smem_u32(sWL) + (uint32_t)(wn * 64 + (sel & 1) * 8 + lr) * XS_ROW + koff2;

    float d[2][8][4];
#pragma unroll
    for (int i = 0; i < 2; i++)
#pragma unroll
        for (int j = 0; j < 8; j++)
#pragma unroll
            for (int q = 0; q < 4; q++) d[i][j][q] = 0.0f;

    float4 pfA[4], pfW[4];
#pragma unroll
    for (int i = 0; i < 4; i++) {
        pfA[i] = *(const float4*)(agp + i * 32 * IDIM);
        pfW[i] = *(const float4*)(wgp + i * 32 * IDIM);
    }

    for (int kc = 0; kc < 16; kc++) {
#pragma unroll
        for (int i = 0; i < 4; i++) {
            int row = srow + i * 32;
            uint2 hi, lo;
            split4(pfA[i], hi, lo);
            *(uint2*)(sAH + row * XS_ROW + sc4 * 2) = hi;
            *(uint2*)(sAL + row * XS_ROW + sc4 * 2) = lo;
            split4(pfW[i], hi, lo);
            *(uint2*)(sWH + row * XS_ROW + sc4 * 2) = hi;
            *(uint2*)(sWL + row * XS_ROW + sc4 * 2) = lo;
        }
        __syncthreads();

        if (kc < 15) {
            const float* an = agp + (kc + 1) * 32;
            const float* wnp = wgp + (kc + 1) * 32;
#pragma unroll
            for (int i = 0; i < 4; i++) {
                pfA[i] = *(const float4*)(an + i * 32 * IDIM);
                pfW[i] = *(const float4*)(wnp + i * 32 * IDIM);
            }
        }

#pragma unroll
        for (int k16 = 0; k16 < 2; k16++) {
            const uint32_t ko = (uint32_t)(k16 * 32);
            uint32_t ah[2][4], al[2][4];
            ldm4(ah[0], aH + ko);
            ldm4(ah[1], aH + ko + 16 * XS_ROW);
            ldm4(al[0], aL + ko);
            ldm4(al[1], aL + ko + 16 * XS_ROW);
#pragma unroll
            for (int bnp = 0; bnp < 4; bnp++) {
                uint32_t bh[4], bl[4];
                ldm4(bh, bH + ko + (uint32_t)(bnp * 16) * XS_ROW);
                mma16816(d[0][2 * bnp],     ah[0], bh[0], bh[2]);
                mma16816(d[0][2 * bnp + 1], ah[0], bh[1], bh[3]);
                mma16816(d[1][2 * bnp],     ah[1], bh[0], bh[2]);
                mma16816(d[1][2 * bnp + 1], ah[1], bh[1], bh[3]);
                mma16816(d[0][2 * bnp],     al[0], bh[0], bh[2]);
                mma16816(d[0][2 * bnp + 1], al[0], bh[1], bh[3]);
                mma16816(d[1][2 * bnp],     al[1], bh[0], bh[2]);
                mma16816(d[1][2 * bnp + 1], al[1], bh[1], bh[3]);
                ldm4(bl, bL + ko + (uint32_t)(bnp * 16) * XS_ROW);
                mma16816(d[0][2 * bnp],     ah[0], bl[0], bl[2]);
                mma16816(d[0][2 * bnp + 1], ah[0], bl[1], bl[3]);
                mma16816(d[1][2 * bnp],     ah[1], bl[0], bl[2]);
                mma16816(d[1][2 * bnp + 1], ah[1], bl[1], bl[3]);
            }
        }
        __syncthreads();
    }

    const int erow = m0 + wm * 32 + (lane >> 2);
    const int ecol = wn * 64 + (lane & 3) * 2;
#pragma unroll
    for (int am = 0; am < 2; am++) {
#pragma unroll
        for (int bn = 0; bn < 8; bn++) {
            int col = ecol + bn * 8;
            float b0 = sBias[col], b1 = sBias[col + 1];
            float* p0 = g_xproj + (size_t)(erow + am * 16) * G4 + n0 + col;
            float* p1 = p0 + 8 * G4;
            *(float2*)p0 = make_float2(d[am][bn][0] + b0, d[am][bn][1] + b1);
            *(float2*)p1 = make_float2(d[am][bn][2] + b0, d[am][bn][3] + b1);
        }
    }
}

// ---------------------------------------------------------------------------
// Kernel 2: recurrence, slice-granular flags + warp-pair role split.
// Grid (32 col-groups cg, 4 batch-groups g). CTA: 16 batches x 16 hcols.
// Pair kw = wid>>1 (K slice of 64 cols); even warp: MMA(nw0)+cell+release;
// odd warp: MMA(nw1)+poll(flag[kw])+LDG+stage+xp.  Double-buffered g_hpack,
// p9 (reuses dead W-staging SMEM) and xp_s.  One __syncthreads per step.
// ---------------------------------------------------------------------------
#define OFF_WHI  0                         // init-only (reused by p9 after)
#define OFF_WLO  66560
#define OFF_P9A  0                         // float [8][1092] = 34944 B
#define OFF_P9B  36864
#define OFF_HHI  133120                    // 16 rows x 1040 B
#define OFF_HLO  149760
#define OFF_XP   166400                    // 2 x float[1024] = 8192 B
#define R_SMEM   174592

__global__ void __launch_bounds__(512, 1) recur_mma_kernel(
    const float* __restrict__ h0, const float* __restrict__ c0,
    const float* __restrict__ Whh, float* __restrict__ out)
{
    extern __shared__ char sm[];

    const int tid  = threadIdx.x;
    const int lane = tid & 31, wid = tid >> 5;
    const int kw = wid >> 1;               // K slice of 64 (0..7)
    const int nw = wid & 1;                // n slice of 32 (0..1); also role
    const int cg = blockIdx.x;
    const int j0 = cg * 16;
    const int B0 = blockIdx.y * 16;
    const int grp = blockIdx.y;
    unsigned int* flagR = &g_barF[(grp * 8 + kw) * 32];         // consume
    unsigned int* flagW = &g_barF[(grp * 8 + (cg >> 2)) * 32];  // produce

    // ---- convert W_hh slice to bf16 hi/lo in SMEM (init only) ----
#pragma unroll 4
    for (int i = 0; i < 16; i++) {
        int idx = tid + i * 512;
        int row = idx >> 7;                // 0..63 (gate*16+jj)
        int f4  = (idx & 127) << 2;
        int gate = row >> 4, jj = row & 15;
        float4 v = *(const float4*)(Whh
                      + (size_t)(gate * HDIM + j0 + jj) * HDIM + f4);
        uint2 hi, lo;
        split4(v, hi, lo);
        *(uint2*)(sm + OFF_WHI + row * 1040 + f4 * 2) = hi;
        *(uint2*)(sm + OFF_WLO + row * 1040 + f4 * 2) = lo;
    }
    __syncthreads();

    // ---- load B (W) fragments into registers (once) ----
    const int lr = lane & 7, sel = lane >> 3;
    uint32_t BH[4][2][4], BL[4][2][4];
#pragma unroll
    for (int ks = 0; ks < 4; ks++)
#pragma unroll
        for (int p = 0; p < 2; p++) {
            uint32_t off = (uint32_t)(nw * 32 + p * 16 + (sel & 1) * 8 + lr) * 1040u
                         + (uint32_t)((sel >> 1) * 16)
                         + (uint32_t)(kw * 128 + ks * 32);
            ldm4(BH[ks][p], smem_u32(sm + OFF_WHI) + off);
            ldm4(BL[ks][p], smem_u32(sm + OFF_WLO) + off);
        }

    // ---- A (h) ldmatrix addressing ----
    const uint32_t aRowOff = (uint32_t)((sel & 1) * 8 + lr) * 1040u
                           + (uint32_t)((sel >> 1) * 16)
                           + (uint32_t)(kw * 128);
    const uint32_t aHiB = smem_u32(sm + OFF_HHI) + aRowOff;
    const uint32_t aLoB = smem_u32(sm + OFF_HLO) + aRowOff;

    float* xp_s = (float*)(sm + OFF_XP);

    // ---- role-specific loop-invariant state ----
    float creg = 0.0f;
    int cb_ = 0, cjj_ = 0;                 // even (cell) warps
    int xb = 0, xg = 0, xf = 0;            // odd (stage) warps

    if (nw == 0) {
        int ct = kw * 32 + lane;           // 0..255
        cb_ = ct >> 4; cjj_ = ct & 15;
        creg = c0[(size_t)(B0 + cb_) * HDIM + j0 + cjj_];
        float hv = h0[(size_t)(B0 + cb_) * HDIM + j0 + cjj_];
        g_hpack[(size_t)(B0 + cb_) * HDIM + j0 + cjj_] = pack_hilo(hv); // buf 0
        __syncwarp();
        if (lane == 0) {
            asm volatile("red.release.gpu.global.add.u32 [%0], %1;"
                         :: "l"(flagW), "r"(1u) : "memory");
        }
    } else {
        int ot = kw * 32 + lane;           // 0..255
        xb = ot >> 4; int q = ot & 15; xg = q >> 2; xf = q & 3;
        // xp for t=1023 -> parity 1
        float4 xv = *(const float4*)(g_xproj
                + ((size_t)(T_STEPS - 1) * BATCH + B0 + xb) * G4
                + xg * HDIM + j0 + xf * 4);
        *(float4*)(xp_s + 1024 + xb * 64 + xg * 16 + xf * 4) = xv;
        // poll h0 availability (init releases: 32)
        unsigned v;
        do {
            asm volatile("ld.acquire.gpu.global.u32 %0, [%1];"
                         : "=r"(v) : "l"(flagR) : "memory");
        } while (v < 32u);
        // stage h0 slice from buf 0
        uint4 pv[8];
#pragma unroll
        for (int j = 0; j < 8; j++) {
            int r = 2 * j + (lane >> 4);
            int c0i = (lane & 15) * 4;
            pv[j] = *(const uint4*)(g_hpack + (size_t)(B0 + r) * HDIM
                                    + kw * 64 + c0i);
        }
#pragma unroll
        for (int j = 0; j < 8; j++) {
            int r = 2 * j + (lane >> 4);
            int c0i = (lane & 15) * 4;
            uint32_t h0_ = prmt(pv[j].x, pv[j].y, 0x5410);
            uint32_t l0_ = prmt(pv[j].x, pv[j].y, 0x7632);
            uint32_t h1_ = prmt(pv[j].z, pv[j].w, 0x5410);
            uint32_t l1_ = prmt(pv[j].z, pv[j].w, 0x7632);
            *(uint2*)(sm + OFF_HHI + r * 1040 + (kw * 64 + c0i) * 2) = make_uint2(h0_, h1_);
            *(uint2*)(sm + OFF_HLO + r * 1040 + (kw * 64 + c0i) * 2) = make_uint2(l0_, l1_);
        }
    }
    __syncthreads();   // W SMEM reads done; p9 region now reusable

    for (int t = T_STEPS - 1; t >= 0; t--) {
        // ---- pair barrier: slice staged (odd) / previous cell done (even) ----
        asm volatile("bar.sync %0, 64;" :: "r"(1 + kw) : "memory");

        // ---- MMA: 4 k16 steps, B from registers ----
        float acc[4][4];
#pragma unroll
        for (int q = 0; q < 4; q++)
#pragma unroll
            for (int i = 0; i < 4; i++) acc[q][i] = 0.0f;
#pragma unroll
        for (int ks = 0; ks < 4; ks++) {
            uint32_t ah[4], al[4];
            ldm4(ah, aHiB + (uint32_t)(ks * 32));
            ldm4(al, aLoB + (uint32_t)(ks * 32));
#pragma unroll
            for (int q = 0; q < 4; q++) {
                const int p = q >> 1, hh = q & 1;
                mma16816(acc[q], ah, BH[ks][p][hh], BH[ks][p][hh + 2]);
                mma16816(acc[q], al, BH[ks][p][hh], BH[ks][p][hh + 2]);
                mma16816(acc[q], ah, BL[ks][p][hh], BL[ks][p][hh + 2]);
            }
        }
        // ---- store partials into parity buffer ----
        float* p9 = (float*)(sm + ((t & 1) ? OFF_P9B : OFF_P9A));
        {
            const int r = lane >> 2;
            const int c2 = (lane & 3) * 2;
            float* base = p9 + kw * 1092;
#pragma unroll
            for (int q = 0; q < 4; q++) {
                int cc = nw * 32 + q * 8 + c2;
                *(float2*)(base + r * 68 + cc)       = make_float2(acc[q][0], acc[q][1]);
                *(float2*)(base + (r + 8) * 68 + cc) = make_float2(acc[q][2], acc[q][3]);
            }
        }
        __syncthreads();

        if (nw == 0) {
            // ---- cell: reduce 8 K-slices + update + release ----
            const float* xps = xp_s + (t & 1) * 1024;
            float pre[4];
#pragma unroll
            for (int g = 0; g < 4; g++) {
                int off = cb_ * 68 + g * 16 + cjj_;
                float s0 = p9[off]            + p9[1092 + off];
                float s1 = p9[2 * 1092 + off] + p9[3 * 1092 + off];
                float s2 = p9[4 * 1092 + off] + p9[5 * 1092 + off];
                float s3 = p9[6 * 1092 + off] + p9[7 * 1092 + off];
                pre[g] = ((s0 + s1) + (s2 + s3)) + xps[cb_ * 64 + g * 16 + cjj_];
            }
            float gi = sigf(pre[0]);
            float gf = sigf(pre[1]);
            float gz = sigf(pre[2]);
            float go = sigf(pre[3]);
            float cn = gf * creg + gz - gi;
            creg = cn;
            float hn = sigf(cn) - go;
            out[(size_t)t * BHD + (size_t)(B0 + cb_) * HDIM + j0 + cjj_] = hn;
            g_hpack[(size_t)(t & 1) * BHD + (size_t)(B0 + cb_) * HDIM + j0 + cjj_]
                = pack_hilo(hn);
            if (t == 0) {
                const size_t base = (size_t)T_STEPS * BHD;
                out[base + (size_t)(B0 + cb_) * HDIM + j0 + cjj_] = hn;
                out[base + BHD + (size_t)(B0 + cb_) * HDIM + j0 + cjj_] = cn;
            }
            __syncwarp();
            if (lane == 0 && t > 0) {
                asm volatile("red.release.gpu.global.add.u32 [%0], %1;"
                             :: "l"(flagW), "r"(1u) : "memory");
            }
        } else if (t > 0) {
            // ---- stage warp: xp(t-1) + poll + stage h(t) ----
            float4 xv = *(const float4*)(g_xproj
                    + ((size_t)(t - 1) * BATCH + B0 + xb) * G4
                    + xg * HDIM + j0 + xf * 4);
            unsigned target = (unsigned)(T_STEPS - t + 1) * 32u;
            unsigned v;
            do {
                asm volatile("ld.acquire.gpu.global.u32 %0, [%1];"
                             : "=r"(v) : "l"(flagR) : "memory");
            } while (v < target);

            const uint32_t* hb = g_hpack + (size_t)(t & 1) * BHD;
            uint4 pv[8];
#pragma unroll
            for (int j = 0; j < 8; j++) {
                int r = 2 * j + (lane >> 4);
                int c0i = (lane & 15) * 4;
                pv[j] = *(const uint4*)(hb + (size_t)(B0 + r) * HDIM
                                        + kw * 64 + c0i);
            }
#pragma unroll
            for (int j = 0; j < 8; j++) {
                int r = 2 * j + (lane >> 4);
                int c0i = (lane & 15) * 4;
                uint32_t h0_ = prmt(pv[j].x, pv[j].y, 0x5410);
                uint32_t l0_ = prmt(pv[j].x, pv[j].y, 0x7632);
                uint32_t h1_ = prmt(pv[j].z, pv[j].w, 0x5410);
                uint32_t l1_ = prmt(pv[j].z, pv[j].w, 0x7632);
                *(uint2*)(sm + OFF_HHI + r * 1040 + (kw * 64 + c0i) * 2) = make_uint2(h0_, h1_);
                *(uint2*)(sm + OFF_HLO + r * 1040 + (kw * 64 + c0i) * 2) = make_uint2(l0_, l1_);
            }
            *(float4*)(xp_s + ((t - 1) & 1) * 1024 + xb * 64 + xg * 16 + xf * 4) = xv;
        }
    }

    // ---- self-reset of counters (after ALL 128 CTAs finish) ----
    __syncthreads();
    if (tid == 0) {
        unsigned v = atomicAdd(&g_done, 1u);
        if (v == 127u) {
            for (int i = 0; i < 32; i++)
                atomicExch(&g_barF[i * 32], 0u);
            atomicExch(&g_done, 0u);
        }
    }
}

// ---------------------------------------------------------------------------
extern "C" void kernel_launch(void* const* d_in, const int* in_sizes, int n_in,
                              void* d_out, int out_size)
{
    const float* input = (const float*)d_in[0];
    const float* h0    = (const float*)d_in[1];
    const float* c0    = (const float*)d_in[2];
    const float* Wih   = (const float*)d_in[3];
    const float* Whh   = (const float*)d_in[4];
    const float* bih   = (const float*)d_in[5];
    const float* bhh   = (const float*)d_in[6];
    float* out = (float*)d_out;

    static int configured = 0;
    if (!configured) {
        cudaFuncSetAttribute(recur_mma_kernel,
                             cudaFuncAttributeMaxDynamicSharedMemorySize,
                             R_SMEM);
        configured = 1;
    }

    xproj_mma_kernel<<<dim3(G4 / 128, MTOT / 128), 256>>>(input, Wih, bih, bhh);
    recur_mma_kernel<<<dim3(HDIM / 16, BATCH / 16), 512, R_SMEM>>>(
        h0, c0, Whh, out);
}

// round 12
// speedup vs baseline: 1.3471x; 1.1208x over previous
#include <cuda_runtime.h>
#include <cuda_bf16.h>
#include <cuda_fp16.h>
#include <math.h>
#include <stdint.h>

#define T_STEPS 1024
#define BATCH   64
#define IDIM    512
#define HDIM    512
#define G4      2048   // 4*H
#define MTOT    (T_STEPS * BATCH)   // 65536
#define BHD     (BATCH * HDIM)

// ---- device-global scratch (no allocs allowed) ----
__device__ float          g_xproj[(size_t)MTOT * G4];   // 512 MB
__device__ unsigned short g_hpackH[2 * BHD];            // double-buffered fp16 h
__device__ unsigned int   g_barF[4 * 8 * 32];           // per-(group, K-slice) flags
__device__ unsigned int   g_done;

__device__ __forceinline__ float sigf(float x) {
    return __fdividef(1.0f, 1.0f + __expf(-x));
}

// ---------------- helpers ----------------
__device__ __forceinline__ uint32_t smem_u32(const void* p) {
    uint32_t a;
    asm("{ .reg .u64 t; cvta.to.shared.u64 t, %1; cvt.u32.u64 %0, t; }"
        : "=r"(a) : "l"(p));
    return a;
}
__device__ __forceinline__ void ldm4(uint32_t* r, uint32_t addr) {
    asm volatile("ldmatrix.sync.aligned.m8n8.x4.shared.b16 {%0,%1,%2,%3}, [%4];"
                 : "=r"(r[0]), "=r"(r[1]), "=r"(r[2]), "=r"(r[3]) : "r"(addr));
}
__device__ __forceinline__ void mma16816(float* d, const uint32_t* a,
                                         uint32_t b0, uint32_t b1) {
    asm volatile(
        "mma.sync.aligned.m16n8k16.row.col.f32.bf16.bf16.f32 "
        "{%0,%1,%2,%3}, {%4,%5,%6,%7}, {%8,%9}, {%0,%1,%2,%3};"
        : "+f"(d[0]), "+f"(d[1]), "+f"(d[2]), "+f"(d[3])
        : "r"(a[0]), "r"(a[1]), "r"(a[2]), "r"(a[3]), "r"(b0), "r"(b1));
}
__device__ __forceinline__ void mma16816h(float* d, const uint32_t* a,
                                          uint32_t b0, uint32_t b1) {
    asm volatile(
        "mma.sync.aligned.m16n8k16.row.col.f32.f16.f16.f32 "
        "{%0,%1,%2,%3}, {%4,%5,%6,%7}, {%8,%9}, {%0,%1,%2,%3};"
        : "+f"(d[0]), "+f"(d[1]), "+f"(d[2]), "+f"(d[3])
        : "r"(a[0]), "r"(a[1]), "r"(a[2]), "r"(a[3]), "r"(b0), "r"(b1));
}
// bf16 split (xproj)
__device__ __forceinline__ void split4(const float4 v, uint2& hi, uint2& lo) {
    __nv_bfloat16 h0 = __float2bfloat16(v.x), h1 = __float2bfloat16(v.y);
    __nv_bfloat16 h2 = __float2bfloat16(v.z), h3 = __float2bfloat16(v.w);
    __nv_bfloat16 l0 = __float2bfloat16(v.x - __bfloat162float(h0));
    __nv_bfloat16 l1 = __float2bfloat16(v.y - __bfloat162float(h1));
    __nv_bfloat16 l2 = __float2bfloat16(v.z - __bfloat162float(h2));
    __nv_bfloat16 l3 = __float2bfloat16(v.w - __bfloat162float(h3));
    hi.x = (uint32_t)__bfloat16_as_ushort(h0) |
           ((uint32_t)__bfloat16_as_ushort(h1) << 16);
    hi.y = (uint32_t)__bfloat16_as_ushort(h2) |
           ((uint32_t)__bfloat16_as_ushort(h3) << 16);
    lo.x = (uint32_t)__bfloat16_as_ushort(l0) |
           ((uint32_t)__bfloat16_as_ushort(l1) << 16);
    lo.y = (uint32_t)__bfloat16_as_ushort(l2) |
           ((uint32_t)__bfloat16_as_ushort(l3) << 16);
}
// fp16 split (recur W, pre-scaled)
__device__ __forceinline__ void split4h(const float4 v, uint2& hi, uint2& lo) {
    __half h0 = __float2half_rn(v.x), h1 = __float2half_rn(v.y);
    __half h2 = __float2half_rn(v.z), h3 = __float2half_rn(v.w);
    __half l0 = __float2half_rn(v.x - __half2float(h0));
    __half l1 = __float2half_rn(v.y - __half2float(h1));
    __half l2 = __float2half_rn(v.z - __half2float(h2));
    __half l3 = __float2half_rn(v.w - __half2float(h3));
    hi.x = (uint32_t)__half_as_ushort(h0) | ((uint32_t)__half_as_ushort(h1) << 16);
    hi.y = (uint32_t)__half_as_ushort(h2) | ((uint32_t)__half_as_ushort(h3) << 16);
    lo.x = (uint32_t)__half_as_ushort(l0) | ((uint32_t)__half_as_ushort(l1) << 16);
    lo.y = (uint32_t)__half_as_ushort(l2) | ((uint32_t)__half_as_ushort(l3) << 16);
}

// ---------------------------------------------------------------------------
// Kernel 1: x_proj via bf16 hi/lo-split HMMA (UNCHANGED, passing)
// ---------------------------------------------------------------------------
#define XS_ROW   80
#define XS_BUF   (128 * XS_ROW)
__global__ void __launch_bounds__(256, 1) xproj_mma_kernel(
    const float* __restrict__ A, const float* __restrict__ W,
    const float* __restrict__ bih, const float* __restrict__ bhh)
{
    __shared__ __align__(16) char sAH[XS_BUF];
    __shared__ __align__(16) char sAL[XS_BUF];
    __shared__ __align__(16) char sWH[XS_BUF];
    __shared__ __align__(16) char sWL[XS_BUF];
    __shared__ float sBias[128];

    const int tid = threadIdx.x;
    const int n0 = blockIdx.x * 128;
    const int m0 = blockIdx.y * 128;
    const int lane = tid & 31, wid = tid >> 5;
    const int wm = wid >> 1, wn = wid & 1;

    if (tid < 128) sBias[tid] = bih[n0 + tid] + bhh[n0 + tid];

    const int srow = tid >> 3;
    const int sc4  = (tid & 7) << 2;
    const float* agp = A + (size_t)(m0 + srow) * IDIM + sc4;
    const float* wgp = W + (size_t)(n0 + srow) * IDIM + sc4;

    const int lr = lane & 7, sel = lane >> 3;
    const int koff2 = ((sel >> 1) * 8) * 2;
    const uint32_t aH = smem_u32(sAH) + (uint32_t)(wm * 32 + (sel & 1) * 8 + lr) * XS_ROW + koff2;
    const uint32_t aL = smem_u32(sAL) + (uint32_t)(wm * 32 + (sel & 1) * 8 + lr) * XS_ROW + koff2;
    const uint32_t bH = smem_u32(sWH) + (uint32_t)(wn * 64 + (sel & 1) * 8 + lr) * XS_ROW + koff2;
    const uint32_t bL = smem_u32(sWL) + (uint32_t)(wn * 64 + (sel & 1) * 8 + lr) * XS_ROW + koff2;

    float d[2][8][4];
#pragma unroll
    for (int i = 0; i < 2; i++)
#pragma unroll
        for (int j = 0; j < 8; j++)
#pragma unroll
            for (int q = 0; q < 4; q++) d[i][j][q] = 0.0f;

    float4 pfA[4], pfW[4];
#pragma unroll
    for (int i = 0; i < 4; i++) {
        pfA[i] = *(const float4*)(agp + i * 32 * IDIM);
        pfW[i] = *(const float4*)(wgp + i * 32 * IDIM);
    }

    for (int kc = 0; kc < 16; kc++) {
#pragma unroll
        for (int i = 0; i < 4; i++) {
            int row = srow + i * 32;
            uint2 hi, lo;
            split4(pfA[i], hi, lo);
            *(uint2*)(sAH + row * XS_ROW + sc4 * 2) = hi;
            *(uint2*)(sAL + row * XS_ROW + sc4 * 2) = lo;
            split4(pfW[i], hi, lo);
            *(uint2*)(sWH + row * XS_ROW + sc4 * 2) = hi;
            *(uint2*)(sWL + row * XS_ROW + sc4 * 2) = lo;
        }
        __syncthreads();

        if (kc < 15) {
            const float* an = agp + (kc + 1) * 32;
            const float* wnp = wgp + (kc + 1) * 32;
#pragma unroll
            for (int i = 0; i < 4; i++) {
                pfA[i] = *(const float4*)(an + i * 32 * IDIM);
                pfW[i] = *(const float4*)(wnp + i * 32 * IDIM);
            }
        }

#pragma unroll
        for (int k16 = 0; k16 < 2; k16++) {
            const uint32_t ko = (uint32_t)(k16 * 32);
            uint32_t ah[2][4], al[2][4];
            ldm4(ah[0], aH + ko);
            ldm4(ah[1], aH + ko + 16 * XS_ROW);
            ldm4(al[0], aL + ko);
            ldm4(al[1], aL + ko + 16 * XS_ROW);
#pragma unroll
            for (int bnp = 0; bnp < 4; bnp++) {
                uint32_t bh[4], bl[4];
                ldm4(bh, bH + ko + (uint32_t)(bnp * 16) * XS_ROW);
                mma16816(d[0][2 * bnp],     ah[0], bh[0], bh[2]);
                mma16816(d[0][2 * bnp + 1], ah[0], bh[1], bh[3]);
                mma16816(d[1][2 * bnp],     ah[1], bh[0], bh[2]);
                mma16816(d[1][2 * bnp + 1], ah[1], bh[1], bh[3]);
                mma16816(d[0][2 * bnp],     al[0], bh[0], bh[2]);
                mma16816(d[0][2 * bnp + 1], al[0], bh[1], bh[3]);
                mma16816(d[1][2 * bnp],     al[1], bh[0], bh[2]);
                mma16816(d[1][2 * bnp + 1], al[1], bh[1], bh[3]);
                ldm4(bl, bL + ko + (uint32_t)(bnp * 16) * XS_ROW);
                mma16816(d[0][2 * bnp],     ah[0], bl[0], bl[2]);
                mma16816(d[0][2 * bnp + 1], ah[0], bl[1], bl[3]);
                mma16816(d[1][2 * bnp],     ah[1], bl[0], bl[2]);
                mma16816(d[1][2 * bnp + 1], ah[1], bl[1], bl[3]);
            }
        }
        __syncthreads();
    }

    const int erow = m0 + wm * 32 + (lane >> 2);
    const int ecol = wn * 64 + (lane & 3) * 2;
#pragma unroll
    for (int am = 0; am < 2; am++) {
#pragma unroll
        for (int bn = 0; bn < 8; bn++) {
            int col = ecol + bn * 8;
            float b0 = sBias[col], b1 = sBias[col + 1];
            float* p0 = g_xproj + (size_t)(erow + am * 16) * G4 + n0 + col;
            float* p1 = p0 + 8 * G4;
            *(float2*)p0 = make_float2(d[am][bn][0] + b0, d[am][bn][1] + b1);
            *(float2*)p1 = make_float2(d[am][bn][2] + b0, d[am][bn][3] + b1);
        }
    }
}

// ---------------------------------------------------------------------------
// Kernel 2: recurrence, fp16 2-term (W pre-scaled x16, split hi/lo; h single
// fp16). Slice flags + warp-pair role split + bar.arrive partials join.
// ---------------------------------------------------------------------------
#define OFF_WHI  0                         // init W hi (reused by p9A after)
#define OFF_WLO  66560                     // init W lo (reused after frag load? NO - p9B at 36864 overlaps WLO? see below)
#define OFF_P9A  0                         // float [8][1092] = 34944 B
#define OFF_P9B  36864                     // 36864..71808 (inside WHI/WLO init zone, reused after)
#define OFF_HHI  133120                    // 16 rows x 1040 B (fp16 h)
#define OFF_XP   166400                    // 2 x float[1024] = 8192 B
#define R_SMEM   174592

__global__ void __launch_bounds__(512, 1) recur_mma_kernel(
    const float* __restrict__ h0, const float* __restrict__ c0,
    const float* __restrict__ Whh, float* __restrict__ out)
{
    extern __shared__ char sm[];

    const int tid  = threadIdx.x;
    const int lane = tid & 31, wid = tid >> 5;
    const int kw = wid >> 1;               // K slice of 64 (0..7)
    const int nw = wid & 1;                // n slice of 32; also role
    const int cg = blockIdx.x;
    const int j0 = cg * 16;
    const int B0 = blockIdx.y * 16;
    const int grp = blockIdx.y;
    unsigned int* flagR = &g_barF[(grp * 8 + kw) * 32];         // consume
    unsigned int* flagW = &g_barF[(grp * 8 + (cg >> 2)) * 32];  // produce

    // ---- convert W_hh slice (x16) to fp16 hi/lo in SMEM (init only) ----
#pragma unroll 4
    for (int i = 0; i < 16; i++) {
        int idx = tid + i * 512;
        int row = idx >> 7;                // 0..63 (gate*16+jj)
        int f4  = (idx & 127) << 2;
        int gate = row >> 4, jj = row & 15;
        float4 v = *(const float4*)(Whh
                      + (size_t)(gate * HDIM + j0 + jj) * HDIM + f4);
        v.x *= 16.0f; v.y *= 16.0f; v.z *= 16.0f; v.w *= 16.0f;
        uint2 hi, lo;
        split4h(v, hi, lo);
        *(uint2*)(sm + OFF_WHI + row * 1040 + f4 * 2) = hi;
        *(uint2*)(sm + OFF_WLO + row * 1040 + f4 * 2) = lo;
    }
    __syncthreads();

    // ---- load B (W) fragments into registers (once) ----
    const int lr = lane & 7, sel = lane >> 3;
    uint32_t BH[4][2][4], BL[4][2][4];
#pragma unroll
    for (int ks = 0; ks < 4; ks++)
#pragma unroll
        for (int p = 0; p < 2; p++) {
            uint32_t off = (uint32_t)(nw * 32 + p * 16 + (sel & 1) * 8 + lr) * 1040u
                         + (uint32_t)((sel >> 1) * 16)
                         + (uint32_t)(kw * 128 + ks * 32);
            ldm4(BH[ks][p], smem_u32(sm + OFF_WHI) + off);
            ldm4(BL[ks][p], smem_u32(sm + OFF_WLO) + off);
        }

    // ---- A (h) ldmatrix addressing (single fp16 plane) ----
    const uint32_t aRowOff = (uint32_t)((sel & 1) * 8 + lr) * 1040u
                           + (uint32_t)((sel >> 1) * 16)
                           + (uint32_t)(kw * 128);
    const uint32_t aHiB = smem_u32(sm + OFF_HHI) + aRowOff;

    float* xp_s = (float*)(sm + OFF_XP);

    // ---- role-specific loop-invariant state ----
    float creg = 0.0f;
    int cb_ = 0, cjj_ = 0;                 // even (cell) warps
    int xb = 0, xg = 0, xf = 0;            // odd (stage) warps

    if (nw == 0) {
        int ct = kw * 32 + lane;           // 0..255
        cb_ = ct >> 4; cjj_ = ct & 15;
        creg = c0[(size_t)(B0 + cb_) * HDIM + j0 + cjj_];
        float hv = h0[(size_t)(B0 + cb_) * HDIM + j0 + cjj_];
        g_hpackH[(size_t)(B0 + cb_) * HDIM + j0 + cjj_]
            = __half_as_ushort(__float2half_rn(hv));            // buf 0
        __syncwarp();
        if (lane == 0) {
            asm volatile("red.release.gpu.global.add.u32 [%0], %1;"
                         :: "l"(flagW), "r"(1u) : "memory");
        }
    } else {
        int ot = kw * 32 + lane;           // 0..255
        xb = ot >> 4; int q = ot & 15; xg = q >> 2; xf = q & 3;
        float4 xv = *(const float4*)(g_xproj
                + ((size_t)(T_STEPS - 1) * BATCH + B0 + xb) * G4
                + xg * HDIM + j0 + xf * 4);
        *(float4*)(xp_s + 1024 + xb * 64 + xg * 16 + xf * 4) = xv;
        // poll h0 availability (init releases: 32)
        unsigned v;
        do {
            asm volatile("ld.acquire.gpu.global.u32 %0, [%1];"
                         : "=r"(v) : "l"(flagR) : "memory");
        } while (v < 32u);
        // stage h0 slice (fp16, 2KB): 4 x uint4 per lane
        uint4 pv[4];
#pragma unroll
        for (int j = 0; j < 4; j++) {
            int idx = j * 32 + lane;
            int r = idx >> 3, c16 = (idx & 7) * 8;
            pv[j] = *(const uint4*)(g_hpackH + (size_t)(B0 + r) * HDIM
                                    + kw * 64 + c16);
        }
#pragma unroll
        for (int j = 0; j < 4; j++) {
            int idx = j * 32 + lane;
            int r = idx >> 3, c16 = (idx & 7) * 8;
            *(uint4*)(sm + OFF_HHI + r * 1040 + (kw * 64 + c16) * 2) = pv[j];
        }
    }
    __syncthreads();   // W SMEM reads done; p9 region now reusable

    for (int t = T_STEPS - 1; t >= 0; t--) {
        // ---- pair barrier: slice staged (odd) / previous cell done (even) ----
        asm volatile("bar.sync %0, 64;" :: "r"(1 + kw) : "memory");

        // ---- MMA: 4 k16 steps x 2 terms, A hoisted, B from registers ----
        uint32_t ah[4][4];
#pragma unroll
        for (int ks = 0; ks < 4; ks++)
            ldm4(ah[ks], aHiB + (uint32_t)(ks * 32));
        float acc[4][4];
#pragma unroll
        for (int q = 0; q < 4; q++)
#pragma unroll
            for (int i = 0; i < 4; i++) acc[q][i] = 0.0f;
#pragma unroll
        for (int ks = 0; ks < 4; ks++) {
#pragma unroll
            for (int q = 0; q < 4; q++) {
                const int p = q >> 1, hh = q & 1;
                mma16816h(acc[q], ah[ks], BH[ks][p][hh], BH[ks][p][hh + 2]);
                mma16816h(acc[q], ah[ks], BL[ks][p][hh], BL[ks][p][hh + 2]);
            }
        }
        // ---- store partials into parity buffer ----
        float* p9 = (float*)(sm + ((t & 1) ? OFF_P9B : OFF_P9A));
        {
            const int r = lane >> 2;
            const int c2 = (lane & 3) * 2;
            float* base = p9 + kw * 1092;
#pragma unroll
            for (int q = 0; q < 4; q++) {
                int cc = nw * 32 + q * 8 + c2;
                *(float2*)(base + r * 68 + cc)       = make_float2(acc[q][0], acc[q][1]);
                *(float2*)(base + (r + 8) * 68 + cc) = make_float2(acc[q][2], acc[q][3]);
            }
        }

        if (nw == 0) {
            // cell warps wait for everyone's partials
            asm volatile("bar.sync 9, 512;" ::: "memory");
            const float* xps = xp_s + (t & 1) * 1024;
            float pre[4];
#pragma unroll
            for (int g = 0; g < 4; g++) {
                int off = cb_ * 68 + g * 16 + cjj_;
                float s0 = p9[off]            + p9[1092 + off];
                float s1 = p9[2 * 1092 + off] + p9[3 * 1092 + off];
                float s2 = p9[4 * 1092 + off] + p9[5 * 1092 + off];
                float s3 = p9[6 * 1092 + off] + p9[7 * 1092 + off];
                pre[g] = 0.0625f * ((s0 + s1) + (s2 + s3))
                       + xps[cb_ * 64 + g * 16 + cjj_];
            }
            float gi = sigf(pre[0]);
            float gf = sigf(pre[1]);
            float gz = sigf(pre[2]);
            float go = sigf(pre[3]);
            float cn = gf * creg + gz - gi;
            creg = cn;
            float hn = sigf(cn) - go;
            // publish h first, release, THEN bulk output stores
            g_hpackH[(size_t)(t & 1) * BHD + (size_t)(B0 + cb_) * HDIM + j0 + cjj_]
                = __half_as_ushort(__float2half_rn(hn));
            __syncwarp();
            if (lane == 0 && t > 0) {
                asm volatile("red.release.gpu.global.add.u32 [%0], %1;"
                             :: "l"(flagW), "r"(1u) : "memory");
            }
            out[(size_t)t * BHD + (size_t)(B0 + cb_) * HDIM + j0 + cjj_] = hn;
            if (t == 0) {
                const size_t base = (size_t)T_STEPS * BHD;
                out[base + (size_t)(B0 + cb_) * HDIM + j0 + cjj_] = hn;
                out[base + BHD + (size_t)(B0 + cb_) * HDIM + j0 + cjj_] = cn;
            }
        } else {
            // stage warps: non-blocking arrive, then fetch next step's inputs
            asm volatile("bar.arrive 9, 512;" ::: "memory");
            if (t > 0) {
                float4 xv = *(const float4*)(g_xproj
                        + ((size_t)(t - 1) * BATCH + B0 + xb) * G4
                        + xg * HDIM + j0 + xf * 4);
                unsigned target = (unsigned)(T_STEPS - t + 1) * 32u;
                unsigned v;
                do {
                    asm volatile("ld.acquire.gpu.global.u32 %0, [%1];"
                                 : "=r"(v) : "l"(flagR) : "memory");
                } while (v < target);

                const unsigned short* hb = g_hpackH + (size_t)(t & 1) * BHD;
                uint4 pv[4];
#pragma unroll
                for (int j = 0; j < 4; j++) {
                    int idx = j * 32 + lane;
                    int r = idx >> 3, c16 = (idx & 7) * 8;
                    pv[j] = *(const uint4*)(hb + (size_t)(B0 + r) * HDIM
                                            + kw * 64 + c16);
                }
#pragma unroll
                for (int j = 0; j < 4; j++) {
                    int idx = j * 32 + lane;
                    int r = idx >> 3, c16 = (idx & 7) * 8;
                    *(uint4*)(sm + OFF_HHI + r * 1040 + (kw * 64 + c16) * 2) = pv[j];
                }
                *(float4*)(xp_s + ((t - 1) & 1) * 1024 + xb * 64 + xg * 16 + xf * 4) = xv;
            }
        }
    }

    // ---- self-reset of counters (after ALL 128 CTAs finish) ----
    __syncthreads();
    if (tid == 0) {
        unsigned v = atomicAdd(&g_done, 1u);
        if (v == 127u) {
            for (int i = 0; i < 32; i++)
                atomicExch(&g_barF[i * 32], 0u);
            atomicExch(&g_done, 0u);
        }
    }
}

// ---------------------------------------------------------------------------
extern "C" void kernel_launch(void* const* d_in, const int* in_sizes, int n_in,
                              void* d_out, int out_size)
{
    const float* input = (const float*)d_in[0];
    const float* h0    = (const float*)d_in[1];
    const float* c0    = (const float*)d_in[2];
    const float* Wih   = (const float*)d_in[3];
    const float* Whh   = (const float*)d_in[4];
    const float* bih   = (const float*)d_in[5];
    const float* bhh   = (const float*)d_in[6];
    float* out = (float*)d_out;

    static int configured = 0;
    if (!configured) {
        cudaFuncSetAttribute(recur_mma_kernel,
                             cudaFuncAttributeMaxDynamicSharedMemorySize,
                             R_SMEM);
        configured = 1;
    }

    xproj_mma_kernel<<<dim3(G4 / 128, MTOT / 128), 256>>>(input, Wih, bih, bhh);
    recur_mma_kernel<<<dim3(HDIM / 16, BATCH / 16), 512, R_SMEM>>>(
        h0, c0, Whh, out);
}

// round 13
// speedup vs baseline: 1.5630x; 1.1603x over previous
#include <cuda_runtime.h>
#include <cuda_bf16.h>
#include <cuda_fp16.h>
#include <math.h>
#include <stdint.h>

#define T_STEPS 1024
#define BATCH   64
#define IDIM    512
#define HDIM    512
#define G4      2048   // 4*H
#define MTOT    (T_STEPS * BATCH)   // 65536
#define BHD     (BATCH * HDIM)

// ---- device-global scratch (no allocs allowed) ----
__device__ float          g_xproj[(size_t)MTOT * G4];   // 512 MB
__device__ unsigned short g_hpackH[2 * BHD];            // double-buffered fp16 h
__device__ unsigned int   g_barF[4 * 8 * 32];           // per-(group, K-slice) flags
__device__ unsigned int   g_done;

__device__ __forceinline__ float sigf(float x) {
    return __fdividef(1.0f, 1.0f + __expf(-x));
}

// ---------------- helpers ----------------
__device__ __forceinline__ uint32_t smem_u32(const void* p) {
    uint32_t a;
    asm("{ .reg .u64 t; cvta.to.shared.u64 t, %1; cvt.u32.u64 %0, t; }"
        : "=r"(a) : "l"(p));
    return a;
}
__device__ __forceinline__ void ldm4(uint32_t* r, uint32_t addr) {
    asm volatile("ldmatrix.sync.aligned.m8n8.x4.shared.b16 {%0,%1,%2,%3}, [%4];"
                 : "=r"(r[0]), "=r"(r[1]), "=r"(r[2]), "=r"(r[3]) : "r"(addr));
}
__device__ __forceinline__ void mma16816h(float* d, const uint32_t* a,
                                          uint32_t b0, uint32_t b1) {
    asm volatile(
        "mma.sync.aligned.m16n8k16.row.col.f32.f16.f16.f32 "
        "{%0,%1,%2,%3}, {%4,%5,%6,%7}, {%8,%9}, {%0,%1,%2,%3};"
        : "+f"(d[0]), "+f"(d[1]), "+f"(d[2]), "+f"(d[3])
        : "r"(a[0]), "r"(a[1]), "r"(a[2]), "r"(a[3]), "r"(b0), "r"(b1));
}
// fp16 split of a (pre-scaled) float4 into hi/lo packed pairs
__device__ __forceinline__ void split4h(const float4 v, uint2& hi, uint2& lo) {
    __half h0 = __float2half_rn(v.x), h1 = __float2half_rn(v.y);
    __half h2 = __float2half_rn(v.z), h3 = __float2half_rn(v.w);
    __half l0 = __float2half_rn(v.x - __half2float(h0));
    __half l1 = __float2half_rn(v.y - __half2float(h1));
    __half l2 = __float2half_rn(v.z - __half2float(h2));
    __half l3 = __float2half_rn(v.w - __half2float(h3));
    hi.x = (uint32_t)__half_as_ushort(h0) | ((uint32_t)__half_as_ushort(h1) << 16);
    hi.y = (uint32_t)__half_as_ushort(h2) | ((uint32_t)__half_as_ushort(h3) << 16);
    lo.x = (uint32_t)__half_as_ushort(l0) | ((uint32_t)__half_as_ushort(l1) << 16);
    lo.y = (uint32_t)__half_as_ushort(l2) | ((uint32_t)__half_as_ushort(l3) << 16);
}
// plain fp16 convert of float4 -> packed uint2
__device__ __forceinline__ uint2 cvt4h(const float4 v) {
    __half2 p0 = __floats2half2_rn(v.x, v.y);
    __half2 p1 = __floats2half2_rn(v.z, v.w);
    uint2 r;
    r.x = *reinterpret_cast<const uint32_t*>(&p0);
    r.y = *reinterpret_cast<const uint32_t*>(&p1);
    return r;
}

// ---------------------------------------------------------------------------
// Kernel 1: x_proj via fp16 2-term HMMA.
// A single fp16; W pre-scaled x256, split fp16 hi/lo. D = (Ah*Wh + Ah*Wl)/256
// + bias.  Tile 128x128, 8 warps 4(M)x2(N), K chunks of 32.
// ---------------------------------------------------------------------------
#define XS_ROW   80
#define XS_BUF   (128 * XS_ROW)
#define WSCALE_INV 0.00390625f    // 1/256
__global__ void __launch_bounds__(256, 1) xproj_mma_kernel(
    const float* __restrict__ A, const float* __restrict__ W,
    const float* __restrict__ bih, const float* __restrict__ bhh)
{
    __shared__ __align__(16) char sA [XS_BUF];
    __shared__ __align__(16) char sWH[XS_BUF];
    __shared__ __align__(16) char sWL[XS_BUF];
    __shared__ float sBias[128];

    const int tid = threadIdx.x;
    const int n0 = blockIdx.x * 128;
    const int m0 = blockIdx.y * 128;
    const int lane = tid & 31, wid = tid >> 5;
    const int wm = wid >> 1, wn = wid & 1;

    if (tid < 128) sBias[tid] = bih[n0 + tid] + bhh[n0 + tid];

    const int srow = tid >> 3;
    const int sc4  = (tid & 7) << 2;
    const float* agp = A + (size_t)(m0 + srow) * IDIM + sc4;
    const float* wgp = W + (size_t)(n0 + srow) * IDIM + sc4;

    const int lr = lane & 7, sel = lane >> 3;
    const int koff2 = ((sel >> 1) * 8) * 2;
    const uint32_t aB = smem_u32(sA)  + (uint32_t)(wm * 32 + (sel & 1) * 8 + lr) * XS_ROW + koff2;
    const uint32_t bH = smem_u32(sWH) + (uint32_t)(wn * 64 + (sel & 1) * 8 + lr) * XS_ROW + koff2;
    const uint32_t bL = smem_u32(sWL) + (uint32_t)(wn * 64 + (sel & 1) * 8 + lr) * XS_ROW + koff2;

    float d[2][8][4];
#pragma unroll
    for (int i = 0; i < 2; i++)
#pragma unroll
        for (int j = 0; j < 8; j++)
#pragma unroll
            for (int q = 0; q < 4; q++) d[i][j][q] = 0.0f;

    float4 pfA[4], pfW[4];
#pragma unroll
    for (int i = 0; i < 4; i++) {
        pfA[i] = *(const float4*)(agp + i * 32 * IDIM);
        pfW[i] = *(const float4*)(wgp + i * 32 * IDIM);
    }

    for (int kc = 0; kc < 16; kc++) {
        // ---- stage: A -> fp16, W*256 -> fp16 hi/lo ----
#pragma unroll
        for (int i = 0; i < 4; i++) {
            int row = srow + i * 32;
            *(uint2*)(sA + row * XS_ROW + sc4 * 2) = cvt4h(pfA[i]);
            float4 w = pfW[i];
            w.x *= 256.0f; w.y *= 256.0f; w.z *= 256.0f; w.w *= 256.0f;
            uint2 hi, lo;
            split4h(w, hi, lo);
            *(uint2*)(sWH + row * XS_ROW + sc4 * 2) = hi;
            *(uint2*)(sWL + row * XS_ROW + sc4 * 2) = lo;
        }
        __syncthreads();

        if (kc < 15) {
            const float* an  = agp + (kc + 1) * 32;
            const float* wnp = wgp + (kc + 1) * 32;
#pragma unroll
            for (int i = 0; i < 4; i++) {
                pfA[i] = *(const float4*)(an + i * 32 * IDIM);
                pfW[i] = *(const float4*)(wnp + i * 32 * IDIM);
            }
        }

#pragma unroll
        for (int k16 = 0; k16 < 2; k16++) {
            const uint32_t ko = (uint32_t)(k16 * 32);
            uint32_t a0[4], a1[4];
            ldm4(a0, aB + ko);
            ldm4(a1, aB + ko + 16 * XS_ROW);
#pragma unroll
            for (int bnp = 0; bnp < 4; bnp++) {
                uint32_t bh[4], bl[4];
                ldm4(bh, bH + ko + (uint32_t)(bnp * 16) * XS_ROW);
                mma16816h(d[0][2 * bnp],     a0, bh[0], bh[2]);
                mma16816h(d[0][2 * bnp + 1], a0, bh[1], bh[3]);
                mma16816h(d[1][2 * bnp],     a1, bh[0], bh[2]);
                mma16816h(d[1][2 * bnp + 1], a1, bh[1], bh[3]);
                ldm4(bl, bL + ko + (uint32_t)(bnp * 16) * XS_ROW);
                mma16816h(d[0][2 * bnp],     a0, bl[0], bl[2]);
                mma16816h(d[0][2 * bnp + 1], a0, bl[1], bl[3]);
                mma16816h(d[1][2 * bnp],     a1, bl[0], bl[2]);
                mma16816h(d[1][2 * bnp + 1], a1, bl[1], bl[3]);
            }
        }
        __syncthreads();
    }

    const int erow = m0 + wm * 32 + (lane >> 2);
    const int ecol = wn * 64 + (lane & 3) * 2;
#pragma unroll
    for (int am = 0; am < 2; am++) {
#pragma unroll
        for (int bn = 0; bn < 8; bn++) {
            int col = ecol + bn * 8;
            float b0 = sBias[col], b1 = sBias[col + 1];
            float* p0 = g_xproj + (size_t)(erow + am * 16) * G4 + n0 + col;
            float* p1 = p0 + 8 * G4;
            *(float2*)p0 = make_float2(d[am][bn][0] * WSCALE_INV + b0,
                                       d[am][bn][1] * WSCALE_INV + b1);
            *(float2*)p1 = make_float2(d[am][bn][2] * WSCALE_INV + b0,
                                       d[am][bn][3] * WSCALE_INV + b1);
        }
    }
}

// ---------------------------------------------------------------------------
// Kernel 2: recurrence (UNCHANGED from round 12, passing at 2.71us/step).
// fp16 2-term; slice flags + warp-pair role split + bar.arrive partials join.
// ---------------------------------------------------------------------------
#define OFF_WHI  0
#define OFF_WLO  66560
#define OFF_P9A  0
#define OFF_P9B  36864
#define OFF_HHI  133120
#define OFF_XP   166400
#define R_SMEM   174592

__global__ void __launch_bounds__(512, 1) recur_mma_kernel(
    const float* __restrict__ h0, const float* __restrict__ c0,
    const float* __restrict__ Whh, float* __restrict__ out)
{
    extern __shared__ char sm[];

    const int tid  = threadIdx.x;
    const int lane = tid & 31, wid = tid >> 5;
    const int kw = wid >> 1;
    const int nw = wid & 1;
    const int cg = blockIdx.x;
    const int j0 = cg * 16;
    const int B0 = blockIdx.y * 16;
    const int grp = blockIdx.y;
    unsigned int* flagR = &g_barF[(grp * 8 + kw) * 32];
    unsigned int* flagW = &g_barF[(grp * 8 + (cg >> 2)) * 32];

    // ---- convert W_hh slice (x16) to fp16 hi/lo in SMEM (init only) ----
#pragma unroll 4
    for (int i = 0; i < 16; i++) {
        int idx = tid + i * 512;
        int row = idx >> 7;
        int f4  = (idx & 127) << 2;
        int gate = row >> 4, jj = row & 15;
        float4 v = *(const float4*)(Whh
                      + (size_t)(gate * HDIM + j0 + jj) * HDIM + f4);
        v.x *= 16.0f; v.y *= 16.0f; v.z *= 16.0f; v.w *= 16.0f;
        uint2 hi, lo;
        split4h(v, hi, lo);
        *(uint2*)(sm + OFF_WHI + row * 1040 + f4 * 2) = hi;
        *(uint2*)(sm + OFF_WLO + row * 1040 + f4 * 2) = lo;
    }
    __syncthreads();

    // ---- load B (W) fragments into registers (once) ----
    const int lr = lane & 7, sel = lane >> 3;
    uint32_t BH[4][2][4], BL[4][2][4];
#pragma unroll
    for (int ks = 0; ks < 4; ks++)
#pragma unroll
        for (int p = 0; p < 2; p++) {
            uint32_t off = (uint32_t)(nw * 32 + p * 16 + (sel & 1) * 8 + lr) * 1040u
                         + (uint32_t)((sel >> 1) * 16)
                         + (uint32_t)(kw * 128 + ks * 32);
            ldm4(BH[ks][p], smem_u32(sm + OFF_WHI) + off);
            ldm4(BL[ks][p], smem_u32(sm + OFF_WLO) + off);
        }

    const uint32_t aRowOff = (uint32_t)((sel & 1) * 8 + lr) * 1040u
                           + (uint32_t)((sel >> 1) * 16)
                           + (uint32_t)(kw * 128);
    const uint32_t aHiB = smem_u32(sm + OFF_HHI) + aRowOff;

    float* xp_s = (float*)(sm + OFF_XP);

    float creg = 0.0f;
    int cb_ = 0, cjj_ = 0;
    int xb = 0, xg = 0, xf = 0;

    if (nw == 0) {
        int ct = kw * 32 + lane;
        cb_ = ct >> 4; cjj_ = ct & 15;
        creg = c0[(size_t)(B0 + cb_) * HDIM + j0 + cjj_];
        float hv = h0[(size_t)(B0 + cb_) * HDIM + j0 + cjj_];
        g_hpackH[(size_t)(B0 + cb_) * HDIM + j0 + cjj_]
            = __half_as_ushort(__float2half_rn(hv));
        __syncwarp();
        if (lane == 0) {
            asm volatile("red.release.gpu.global.add.u32 [%0], %1;"
                         :: "l"(flagW), "r"(1u) : "memory");
        }
    } else {
        int ot = kw * 32 + lane;
        xb = ot >> 4; int q = ot & 15; xg = q >> 2; xf = q & 3;
        float4 xv = *(const float4*)(g_xproj
                + ((size_t)(T_STEPS - 1) * BATCH + B0 + xb) * G4
                + xg * HDIM + j0 + xf * 4);
        *(float4*)(xp_s + 1024 + xb * 64 + xg * 16 + xf * 4) = xv;
        unsigned v;
        do {
            asm volatile("ld.acquire.gpu.global.u32 %0, [%1];"
                         : "=r"(v) : "l"(flagR) : "memory");
        } while (v < 32u);
        uint4 pv[4];
#pragma unroll
        for (int j = 0; j < 4; j++) {
            int idx = j * 32 + lane;
            int r = idx >> 3, c16 = (idx & 7) * 8;
            pv[j] = *(const uint4*)(g_hpackH + (size_t)(B0 + r) * HDIM
                                    + kw * 64 + c16);
        }
#pragma unroll
        for (int j = 0; j < 4; j++) {
            int idx = j * 32 + lane;
            int r = idx >> 3, c16 = (idx & 7) * 8;
            *(uint4*)(sm + OFF_HHI + r * 1040 + (kw * 64 + c16) * 2) = pv[j];
        }
    }
    __syncthreads();

    for (int t = T_STEPS - 1; t >= 0; t--) {
        asm volatile("bar.sync %0, 64;" :: "r"(1 + kw) : "memory");

        uint32_t ah[4][4];
#pragma unroll
        for (int ks = 0; ks < 4; ks++)
            ldm4(ah[ks], aHiB + (uint32_t)(ks * 32));
        float acc[4][4];
#pragma unroll
        for (int q = 0; q < 4; q++)
#pragma unroll
            for (int i = 0; i < 4; i++) acc[q][i] = 0.0f;
#pragma unroll
        for (int ks = 0; ks < 4; ks++) {
#pragma unroll
            for (int q = 0; q < 4; q++) {
                const int p = q >> 1, hh = q & 1;
                mma16816h(acc[q], ah[ks], BH[ks][p][hh], BH[ks][p][hh + 2]);
                mma16816h(acc[q], ah[ks], BL[ks][p][hh], BL[ks][p][hh + 2]);
            }
        }
        float* p9 = (float*)(sm + ((t & 1) ? OFF_P9B : OFF_P9A));
        {
            const int r = lane >> 2;
            const int c2 = (lane & 3) * 2;
            float* base = p9 + kw * 1092;
#pragma unroll
            for (int q = 0; q < 4; q++) {
                int cc = nw * 32 + q * 8 + c2;
                *(float2*)(base + r * 68 + cc)       = make_float2(acc[q][0], acc[q][1]);
                *(float2*)(base + (r + 8) * 68 + cc) = make_float2(acc[q][2], acc[q][3]);
            }
        }

        if (nw == 0) {
            asm volatile("bar.sync 9, 512;" ::: "memory");
            const float* xps = xp_s + (t & 1) * 1024;
            float pre[4];
#pragma unroll
            for (int g = 0; g < 4; g++) {
                int off = cb_ * 68 + g * 16 + cjj_;
                float s0 = p9[off]            + p9[1092 + off];
                float s1 = p9[2 * 1092 + off] + p9[3 * 1092 + off];
                float s2 = p9[4 * 1092 + off] + p9[5 * 1092 + off];
                float s3 = p9[6 * 1092 + off] + p9[7 * 1092 + off];
                pre[g] = 0.0625f * ((s0 + s1) + (s2 + s3))
                       + xps[cb_ * 64 + g * 16 + cjj_];
            }
            float gi = sigf(pre[0]);
            float gf = sigf(pre[1]);
            float gz = sigf(pre[2]);
            float go = sigf(pre[3]);
            float cn = gf * creg + gz - gi;
            creg = cn;
            float hn = sigf(cn) - go;
            g_hpackH[(size_t)(t & 1) * BHD + (size_t)(B0 + cb_) * HDIM + j0 + cjj_]
                = __half_as_ushort(__float2half_rn(hn));
            __syncwarp();
            if (lane == 0 && t > 0) {
                asm volatile("red.release.gpu.global.add.u32 [%0], %1;"
                             :: "l"(flagW), "r"(1u) : "memory");
            }
            out[(size_t)t * BHD + (size_t)(B0 + cb_) * HDIM + j0 + cjj_] = hn;
            if (t == 0) {
                const size_t base = (size_t)T_STEPS * BHD;
                out[base + (size_t)(B0 + cb_) * HDIM + j0 + cjj_] = hn;
                out[base + BHD + (size_t)(B0 + cb_) * HDIM + j0 + cjj_] = cn;
            }
        } else {
            asm volatile("bar.arrive 9, 512;" ::: "memory");
            if (t > 0) {
                float4 xv = *(const float4*)(g_xproj
                        + ((size_t)(t - 1) * BATCH + B0 + xb) * G4
                        + xg * HDIM + j0 + xf * 4);
                unsigned target = (unsigned)(T_STEPS - t + 1) * 32u;
                unsigned v;
                do {
                    asm volatile("ld.acquire.gpu.global.u32 %0, [%1];"
                                 : "=r"(v) : "l"(flagR) : "memory");
                } while (v < target);

                const unsigned short* hb = g_hpackH + (size_t)(t & 1) * BHD;
                uint4 pv[4];
#pragma unroll
                for (int j = 0; j < 4; j++) {
                    int idx = j * 32 + lane;
                    int r = idx >> 3, c16 = (idx & 7) * 8;
                    pv[j] = *(const uint4*)(hb + (size_t)(B0 + r) * HDIM
                                            + kw * 64 + c16);
                }
#pragma unroll
                for (int j = 0; j < 4; j++) {
                    int idx = j * 32 + lane;
                    int r = idx >> 3, c16 = (idx & 7) * 8;
                    *(uint4*)(sm + OFF_HHI + r * 1040 + (kw * 64 + c16) * 2) = pv[j];
                }
                *(float4*)(xp_s + ((t - 1) & 1) * 1024 + xb * 64 + xg * 16 + xf * 4) = xv;
            }
        }
    }

    __syncthreads();
    if (tid == 0) {
        unsigned v = atomicAdd(&g_done, 1u);
        if (v == 127u) {
            for (int i = 0; i < 32; i++)
                atomicExch(&g_barF[i * 32], 0u);
            atomicExch(&g_done, 0u);
        }
    }
}

// ---------------------------------------------------------------------------
extern "C" void kernel_launch(void* const* d_in, const int* in_sizes, int n_in,
                              void* d_out, int out_size)
{
    const float* input = (const float*)d_in[0];
    const float* h0    = (const float*)d_in[1];
    const float* c0    = (const float*)d_in[2];
    const float* Wih   = (const float*)d_in[3];
    const float* Whh   = (const float*)d_in[4];
    const float* bih   = (const float*)d_in[5];
    const float* bhh   = (const float*)d_in[6];
    float* out = (float*)d_out;

    static int configured = 0;
    if (!configured) {
        cudaFuncSetAttribute(recur_mma_kernel,
                             cudaFuncAttributeMaxDynamicSharedMemorySize,
                             R_SMEM);
        configured = 1;
    }

    xproj_mma_kernel<<<dim3(G4 / 128, MTOT / 128), 256>>>(input, Wih, bih, bhh);
    recur_mma_kernel<<<dim3(HDIM / 16, BATCH / 16), 512, R_SMEM>>>(
        h0, c0, Whh, out);
}

// round 14
// speedup vs baseline: 1.5884x; 1.0163x over previous
#include <cuda_runtime.h>
#include <cuda_bf16.h>
#include <cuda_fp16.h>
#include <math.h>
#include <stdint.h>

#define T_STEPS 1024
#define BATCH   64
#define IDIM    512
#define HDIM    512
#define G4      2048   // 4*H
#define MTOT    (T_STEPS * BATCH)   // 65536
#define BHD     (BATCH * HDIM)

// ---- device-global scratch (no allocs allowed) ----
__device__ float          g_xproj[(size_t)MTOT * G4];    // 512 MB
__device__ unsigned short g_Ah16[(size_t)MTOT * IDIM];   // 64 MB (A fp16)
__device__ unsigned short g_Wh16[(size_t)G4 * IDIM];     // 2 MB (W*256 hi)
__device__ unsigned short g_Wl16[(size_t)G4 * IDIM];     // 2 MB (W*256 lo)
__device__ unsigned short g_hpackH[2 * BHD];             // double-buffered fp16 h
__device__ unsigned int   g_barF[4 * 8 * 32];            // per-(group,K-slice) flags
__device__ unsigned int   g_done;

__device__ __forceinline__ float sigf(float x) {
    return __fdividef(1.0f, 1.0f + __expf(-x));
}

// ---------------- helpers ----------------
__device__ __forceinline__ uint32_t smem_u32(const void* p) {
    uint32_t a;
    asm("{ .reg .u64 t; cvta.to.shared.u64 t, %1; cvt.u32.u64 %0, t; }"
        : "=r"(a) : "l"(p));
    return a;
}
__device__ __forceinline__ void ldm4(uint32_t* r, uint32_t addr) {
    asm volatile("ldmatrix.sync.aligned.m8n8.x4.shared.b16 {%0,%1,%2,%3}, [%4];"
                 : "=r"(r[0]), "=r"(r[1]), "=r"(r[2]), "=r"(r[3]) : "r"(addr));
}
__device__ __forceinline__ void mma16816h(float* d, const uint32_t* a,
                                          uint32_t b0, uint32_t b1) {
    asm volatile(
        "mma.sync.aligned.m16n8k16.row.col.f32.f16.f16.f32 "
        "{%0,%1,%2,%3}, {%4,%5,%6,%7}, {%8,%9}, {%0,%1,%2,%3};"
        : "+f"(d[0]), "+f"(d[1]), "+f"(d[2]), "+f"(d[3])
        : "r"(a[0]), "r"(a[1]), "r"(a[2]), "r"(a[3]), "r"(b0), "r"(b1));
}
__device__ __forceinline__ void split4h(const float4 v, uint2& hi, uint2& lo) {
    __half h0 = __float2half_rn(v.x), h1 = __float2half_rn(v.y);
    __half h2 = __float2half_rn(v.z), h3 = __float2half_rn(v.w);
    __half l0 = __float2half_rn(v.x - __half2float(h0));
    __half l1 = __float2half_rn(v.y - __half2float(h1));
    __half l2 = __float2half_rn(v.z - __half2float(h2));
    __half l3 = __float2half_rn(v.w - __half2float(h3));
    hi.x = (uint32_t)__half_as_ushort(h0) | ((uint32_t)__half_as_ushort(h1) << 16);
    hi.y = (uint32_t)__half_as_ushort(h2) | ((uint32_t)__half_as_ushort(h3) << 16);
    lo.x = (uint32_t)__half_as_ushort(l0) | ((uint32_t)__half_as_ushort(l1) << 16);
    lo.y = (uint32_t)__half_as_ushort(l2) | ((uint32_t)__half_as_ushort(l3) << 16);
}
__device__ __forceinline__ uint2 cvt4h(const float4 v) {
    __half2 p0 = __floats2half2_rn(v.x, v.y);
    __half2 p1 = __floats2half2_rn(v.z, v.w);
    uint2 r;
    r.x = *reinterpret_cast<const uint32_t*>(&p0);
    r.y = *reinterpret_cast<const uint32_t*>(&p1);
    return r;
}

// ---------------------------------------------------------------------------
// Kernel 0: one-shot conversions. A -> fp16; W*256 -> fp16 hi/lo.
// Each thread handles 8 elements.
// ---------------------------------------------------------------------------
__global__ void __launch_bounds__(256) conv_kernel(
    const float* __restrict__ A, const float* __restrict__ W)
{
    size_t i = (size_t)blockIdx.x * 256 + threadIdx.x;
    size_t base = i * 8;
    if (base < (size_t)MTOT * IDIM) {
        float4 v0 = *(const float4*)(A + base);
        float4 v1 = *(const float4*)(A + base + 4);
        uint2 a = cvt4h(v0), b = cvt4h(v1);
        *(uint4*)(g_Ah16 + base) = make_uint4(a.x, a.y, b.x, b.y);
    }
    if (base < (size_t)G4 * IDIM) {
        float4 w0 = *(const float4*)(W + base);
        float4 w1 = *(const float4*)(W + base + 4);
        w0.x *= 256.0f; w0.y *= 256.0f; w0.z *= 256.0f; w0.w *= 256.0f;
        w1.x *= 256.0f; w1.y *= 256.0f; w1.z *= 256.0f; w1.w *= 256.0f;
        uint2 h0, l0, h1, l1;
        split4h(w0, h0, l0);
        split4h(w1, h1, l1);
        *(uint4*)(g_Wh16 + base) = make_uint4(h0.x, h0.y, h1.x, h1.y);
        *(uint4*)(g_Wl16 + base) = make_uint4(l0.x, l0.y, l1.x, l1.y);
    }
}

// ---------------------------------------------------------------------------
// Kernel 1: x_proj via fp16 2-term HMMA; staging is pure fp16 copies.
// D = (A * Wh + A * Wl)/256 + bias.  Tile 128x128, 8 warps 4(M)x2(N).
// ---------------------------------------------------------------------------
#define XS_ROW   80
#define XS_BUF   (128 * XS_ROW)
#define WSCALE_INV 0.00390625f    // 1/256
__global__ void __launch_bounds__(256, 1) xproj_mma_kernel(
    const float* __restrict__ bih, const float* __restrict__ bhh)
{
    __shared__ __align__(16) char sA [XS_BUF];
    __shared__ __align__(16) char sWH[XS_BUF];
    __shared__ __align__(16) char sWL[XS_BUF];
    __shared__ float sBias[128];

    const int tid = threadIdx.x;
    const int n0 = blockIdx.x * 128;
    const int m0 = blockIdx.y * 128;
    const int lane = tid & 31, wid = tid >> 5;
    const int wm = wid >> 1, wn = wid & 1;

    if (tid < 128) sBias[tid] = bih[n0 + tid] + bhh[n0 + tid];

    const int srow = tid >> 3;
    const int sc4  = (tid & 7) << 2;
    const unsigned short* agp = g_Ah16 + (size_t)(m0 + srow) * IDIM + sc4;
    const unsigned short* whp = g_Wh16 + (size_t)(n0 + srow) * IDIM + sc4;
    const unsigned short* wlp = g_Wl16 + (size_t)(n0 + srow) * IDIM + sc4;

    const int lr = lane & 7, sel = lane >> 3;
    const int koff2 = ((sel >> 1) * 8) * 2;
    const uint32_t aB = smem_u32(sA)  + (uint32_t)(wm * 32 + (sel & 1) * 8 + lr) * XS_ROW + koff2;
    const uint32_t bH = smem_u32(sWH) + (uint32_t)(wn * 64 + (sel & 1) * 8 + lr) * XS_ROW + koff2;
    const uint32_t bL = smem_u32(sWL) + (uint32_t)(wn * 64 + (sel & 1) * 8 + lr) * XS_ROW + koff2;

    float d[2][8][4];
#pragma unroll
    for (int i = 0; i < 2; i++)
#pragma unroll
        for (int j = 0; j < 8; j++)
#pragma unroll
            for (int q = 0; q < 4; q++) d[i][j][q] = 0.0f;

    uint2 pfA[4], pfWh[4], pfWl[4];
#pragma unroll
    for (int i = 0; i < 4; i++) {
        pfA[i]  = *(const uint2*)(agp + (size_t)i * 32 * IDIM);
        pfWh[i] = *(const uint2*)(whp + (size_t)i * 32 * IDIM);
        pfWl[i] = *(const uint2*)(wlp + (size_t)i * 32 * IDIM);
    }

    for (int kc = 0; kc < 16; kc++) {
        // ---- stage: pure copies ----
#pragma unroll
        for (int i = 0; i < 4; i++) {
            int row = srow + i * 32;
            *(uint2*)(sA  + row * XS_ROW + sc4 * 2) = pfA[i];
            *(uint2*)(sWH + row * XS_ROW + sc4 * 2) = pfWh[i];
            *(uint2*)(sWL + row * XS_ROW + sc4 * 2) = pfWl[i];
        }
        __syncthreads();

        if (kc < 15) {
            const unsigned short* an = agp + (kc + 1) * 32;
            const unsigned short* hn = whp + (kc + 1) * 32;
            const unsigned short* ln = wlp + (kc + 1) * 32;
#pragma unroll
            for (int i = 0; i < 4; i++) {
                pfA[i]  = *(const uint2*)(an + (size_t)i * 32 * IDIM);
                pfWh[i] = *(const uint2*)(hn + (size_t)i * 32 * IDIM);
                pfWl[i] = *(const uint2*)(ln + (size_t)i * 32 * IDIM);
            }
        }

#pragma unroll
        for (int k16 = 0; k16 < 2; k16++) {
            const uint32_t ko = (uint32_t)(k16 * 32);
            uint32_t a0[4], a1[4];
            ldm4(a0, aB + ko);
            ldm4(a1, aB + ko + 16 * XS_ROW);
#pragma unroll
            for (int bnp = 0; bnp < 4; bnp++) {
                uint32_t bh[4], bl[4];
                ldm4(bh, bH + ko + (uint32_t)(bnp * 16) * XS_ROW);
                mma16816h(d[0][2 * bnp],     a0, bh[0], bh[2]);
                mma16816h(d[0][2 * bnp + 1], a0, bh[1], bh[3]);
                mma16816h(d[1][2 * bnp],     a1, bh[0], bh[2]);
                mma16816h(d[1][2 * bnp + 1], a1, bh[1], bh[3]);
                ldm4(bl, bL + ko + (uint32_t)(bnp * 16) * XS_ROW);
                mma16816h(d[0][2 * bnp],     a0, bl[0], bl[2]);
                mma16816h(d[0][2 * bnp + 1], a0, bl[1], bl[3]);
                mma16816h(d[1][2 * bnp],     a1, bl[0], bl[2]);
                mma16816h(d[1][2 * bnp + 1], a1, bl[1], bl[3]);
            }
        }
        __syncthreads();
    }

    const int erow = m0 + wm * 32 + (lane >> 2);
    const int ecol = wn * 64 + (lane & 3) * 2;
#pragma unroll
    for (int am = 0; am < 2; am++) {
#pragma unroll
        for (int bn = 0; bn < 8; bn++) {
            int col = ecol + bn * 8;
            float b0 = sBias[col], b1 = sBias[col + 1];
            float* p0 = g_xproj + (size_t)(erow + am * 16) * G4 + n0 + col;
            float* p1 = p0 + 8 * G4;
            *(float2*)p0 = make_float2(d[am][bn][0] * WSCALE_INV + b0,
                                       d[am][bn][1] * WSCALE_INV + b1);
            *(float2*)p1 = make_float2(d[am][bn][2] * WSCALE_INV + b0,
                                       d[am][bn][3] * WSCALE_INV + b1);
        }
    }
}

// ---------------------------------------------------------------------------
// Kernel 2: recurrence (UNCHANGED from round 13, passing at 2.70us/step).
// ---------------------------------------------------------------------------
#define OFF_WHI  0
#define OFF_WLO  66560
#define OFF_P9A  0
#define OFF_P9B  36864
#define OFF_HHI  133120
#define OFF_XP   166400
#define R_SMEM   174592

__global__ void __launch_bounds__(512, 1) recur_mma_kernel(
    const float* __restrict__ h0, const float* __restrict__ c0,
    const float* __restrict__ Whh, float* __restrict__ out)
{
    extern __shared__ char sm[];

    const int tid  = threadIdx.x;
    const int lane = tid & 31, wid = tid >> 5;
    const int kw = wid >> 1;
    const int nw = wid & 1;
    const int cg = blockIdx.x;
    const int j0 = cg * 16;
    const int B0 = blockIdx.y * 16;
    const int grp = blockIdx.y;
    unsigned int* flagR = &g_barF[(grp * 8 + kw) * 32];
    unsigned int* flagW = &g_barF[(grp * 8 + (cg >> 2)) * 32];

    // ---- convert W_hh slice (x16) to fp16 hi/lo in SMEM (init only) ----
#pragma unroll 4
    for (int i = 0; i < 16; i++) {
        int idx = tid + i * 512;
        int row = idx >> 7;
        int f4  = (idx & 127) << 2;
        int gate = row >> 4, jj = row & 15;
        float4 v = *(const float4*)(Whh
                      + (size_t)(gate * HDIM + j0 + jj) * HDIM + f4);
        v.x *= 16.0f; v.y *= 16.0f; v.z *= 16.0f; v.w *= 16.0f;
        uint2 hi, lo;
        split4h(v, hi, lo);
        *(uint2*)(sm + OFF_WHI + row * 1040 + f4 * 2) = hi;
        *(uint2*)(sm + OFF_WLO + row * 1040 + f4 * 2) = lo;
    }
    __syncthreads();

    // ---- load B (W) fragments into registers (once) ----
    const int lr = lane & 7, sel = lane >> 3;
    uint32_t BH[4][2][4], BL[4][2][4];
#pragma unroll
    for (int ks = 0; ks < 4; ks++)
#pragma unroll
        for (int p = 0; p < 2; p++) {
            uint32_t off = (uint32_t)(nw * 32 + p * 16 + (sel & 1) * 8 + lr) * 1040u
                         + (uint32_t)((sel >> 1) * 16)
                         + (uint32_t)(kw * 128 + ks * 32);
            ldm4(BH[ks][p], smem_u32(sm + OFF_WHI) + off);
            ldm4(BL[ks][p], smem_u32(sm + OFF_WLO) + off);
        }

    const uint32_t aRowOff = (uint32_t)((sel & 1) * 8 + lr) * 1040u
                           + (uint32_t)((sel >> 1) * 16)
                           + (uint32_t)(kw * 128);
    const uint32_t aHiB = smem_u32(sm + OFF_HHI) + aRowOff;

    float* xp_s = (float*)(sm + OFF_XP);

    float creg = 0.0f;
    int cb_ = 0, cjj_ = 0;
    int xb = 0, xg = 0, xf = 0;

    if (nw == 0) {
        int ct = kw * 32 + lane;
        cb_ = ct >> 4; cjj_ = ct & 15;
        creg = c0[(size_t)(B0 + cb_) * HDIM + j0 + cjj_];
        float hv = h0[(size_t)(B0 + cb_) * HDIM + j0 + cjj_];
        g_hpackH[(size_t)(B0 + cb_) * HDIM + j0 + cjj_]
            = __half_as_ushort(__float2half_rn(hv));
        __syncwarp();
        if (lane == 0) {
            asm volatile("red.release.gpu.global.add.u32 [%0], %1;"
                         :: "l"(flagW), "r"(1u) : "memory");
        }
    } else {
        int ot = kw * 32 + lane;
        xb = ot >> 4; int q = ot & 15; xg = q >> 2; xf = q & 3;
        float4 xv = *(const float4*)(g_xproj
                + ((size_t)(T_STEPS - 1) * BATCH + B0 + xb) * G4
                + xg * HDIM + j0 + xf * 4);
        *(float4*)(xp_s + 1024 + xb * 64 + xg * 16 + xf * 4) = xv;
        unsigned v;
        do {
            asm volatile("ld.acquire.gpu.global.u32 %0, [%1];"
                         : "=r"(v) : "l"(flagR) : "memory");
        } while (v < 32u);
        uint4 pv[4];
#pragma unroll
        for (int j = 0; j < 4; j++) {
            int idx = j * 32 + lane;
            int r = idx >> 3, c16 = (idx & 7) * 8;
            pv[j] = *(const uint4*)(g_hpackH + (size_t)(B0 + r) * HDIM
                                    + kw * 64 + c16);
        }
#pragma unroll
        for (int j = 0; j < 4; j++) {
            int idx = j * 32 + lane;
            int r = idx >> 3, c16 = (idx & 7) * 8;
            *(uint4*)(sm + OFF_HHI + r * 1040 + (kw * 64 + c16) * 2) = pv[j];
        }
    }
    __syncthreads();

    for (int t = T_STEPS - 1; t >= 0; t--) {
        asm volatile("bar.sync %0, 64;" :: "r"(1 + kw) : "memory");

        uint32_t ah[4][4];
#pragma unroll
        for (int ks = 0; ks < 4; ks++)
            ldm4(ah[ks], aHiB + (uint32_t)(ks * 32));
        float acc[4][4];
#pragma unroll
        for (int q = 0; q < 4; q++)
#pragma unroll
            for (int i = 0; i < 4; i++) acc[q][i] = 0.0f;
#pragma unroll
        for (int ks = 0; ks < 4; ks++) {
#pragma unroll
            for (int q = 0; q < 4; q++) {
                const int p = q >> 1, hh = q & 1;
                mma16816h(acc[q], ah[ks], BH[ks][p][hh], BH[ks][p][hh + 2]);
                mma16816h(acc[q], ah[ks], BL[ks][p][hh], BL[ks][p][hh + 2]);
            }
        }
        float* p9 = (float*)(sm + ((t & 1) ? OFF_P9B : OFF_P9A));
        {
            const int r = lane >> 2;
            const int c2 = (lane & 3) * 2;
            float* base = p9 + kw * 1092;
#pragma unroll
            for (int q = 0; q < 4; q++) {
                int cc = nw * 32 + q * 8 + c2;
                *(float2*)(base + r * 68 + cc)       = make_float2(acc[q][0], acc[q][1]);
                *(float2*)(base + (r + 8) * 68 + cc) = make_float2(acc[q][2], acc[q][3]);
            }
        }

        if (nw == 0) {
            asm volatile("bar.sync 9, 512;" ::: "memory");
            const float* xps = xp_s + (t & 1) * 1024;
            float pre[4];
#pragma unroll
            for (int g = 0; g < 4; g++) {
                int off = cb_ * 68 + g * 16 + cjj_;
                float s0 = p9[off]            + p9[1092 + off];
                float s1 = p9[2 * 1092 + off] + p9[3 * 1092 + off];
                float s2 = p9[4 * 1092 + off] + p9[5 * 1092 + off];
                float s3 = p9[6 * 1092 + off] + p9[7 * 1092 + off];
                pre[g] = 0.0625f * ((s0 + s1) + (s2 + s3))
                       + xps[cb_ * 64 + g * 16 + cjj_];
            }
            float gi = sigf(pre[0]);
            float gf = sigf(pre[1]);
            float gz = sigf(pre[2]);
            float go = sigf(pre[3]);
            float cn = gf * creg + gz - gi;
            creg = cn;
            float hn = sigf(cn) - go;
            g_hpackH[(size_t)(t & 1) * BHD + (size_t)(B0 + cb_) * HDIM + j0 + cjj_]
                = __half_as_ushort(__float2half_rn(hn));
            __syncwarp();
            if (lane == 0 && t > 0) {
                asm volatile("red.release.gpu.global.add.u32 [%0], %1;"
                             :: "l"(flagW), "r"(1u) : "memory");
            }
            out[(size_t)t * BHD + (size_t)(B0 + cb_) * HDIM + j0 + cjj_] = hn;
            if (t == 0) {
                const size_t base = (size_t)T_STEPS * BHD;
                out[base + (size_t)(B0 + cb_) * HDIM + j0 + cjj_] = hn;
                out[base + BHD + (size_t)(B0 + cb_) * HDIM + j0 + cjj_] = cn;
            }
        } else {
            asm volatile("bar.arrive 9, 512;" ::: "memory");
            if (t > 0) {
                float4 xv = *(const float4*)(g_xproj
                        + ((size_t)(t - 1) * BATCH + B0 + xb) * G4
                        + xg * HDIM + j0 + xf * 4);
                unsigned target = (unsigned)(T_STEPS - t + 1) * 32u;
                unsigned v;
                do {
                    asm volatile("ld.acquire.gpu.global.u32 %0, [%1];"
                                 : "=r"(v) : "l"(flagR) : "memory");
                } while (v < target);

                const unsigned short* hb = g_hpackH + (size_t)(t & 1) * BHD;
                uint4 pv[4];
#pragma unroll
                for (int j = 0; j < 4; j++) {
                    int idx = j * 32 + lane;
                    int r = idx >> 3, c16 = (idx & 7) * 8;
                    pv[j] = *(const uint4*)(hb + (size_t)(B0 + r) * HDIM
                                            + kw * 64 + c16);
                }
#pragma unroll
                for (int j = 0; j < 4; j++) {
                    int idx = j * 32 + lane;
                    int r = idx >> 3, c16 = (idx & 7) * 8;
                    *(uint4*)(sm + OFF_HHI + r * 1040 + (kw * 64 + c16) * 2) = pv[j];
                }
                *(float4*)(xp_s + ((t - 1) & 1) * 1024 + xb * 64 + xg * 16 + xf * 4) = xv;
            }
        }
    }

    __syncthreads();
    if (tid == 0) {
        unsigned v = atomicAdd(&g_done, 1u);
        if (v == 127u) {
            for (int i = 0; i < 32; i++)
                atomicExch(&g_barF[i * 32], 0u);
            atomicExch(&g_done, 0u);
        }
    }
}

// ---------------------------------------------------------------------------
extern "C" void kernel_launch(void* const* d_in, const int* in_sizes, int n_in,
                              void* d_out, int out_size)
{
    const float* input = (const float*)d_in[0];
    const float* h0    = (const float*)d_in[1];
    const float* c0    = (const float*)d_in[2];
    const float* Wih   = (const float*)d_in[3];
    const float* Whh   = (const float*)d_in[4];
    const float* bih   = (const float*)d_in[5];
    const float* bhh   = (const float*)d_in[6];
    float* out = (float*)d_out;

    static int configured = 0;
    if (!configured) {
        cudaFuncSetAttribute(recur_mma_kernel,
                             cudaFuncAttributeMaxDynamicSharedMemorySize,
                             R_SMEM);
        configured = 1;
    }

    conv_kernel<<<(int)(((size_t)MTOT * IDIM / 8 + 255) / 256), 256>>>(input, Wih);
    xproj_mma_kernel<<<dim3(G4 / 128, MTOT / 128), 256>>>(bih, bhh);
    recur_mma_kernel<<<dim3(HDIM / 16, BATCH / 16), 512, R_SMEM>>>(
        h0, c0, Whh, out);
}

// round 15
// speedup vs baseline: 1.8942x; 1.1925x over previous
#include <cuda_runtime.h>
#include <cuda_bf16.h>
#include <cuda_fp16.h>
#include <math.h>
#include <stdint.h>

#define T_STEPS 1024
#define BATCH   64
#define IDIM    512
#define HDIM    512
#define G4      2048   // 4*H
#define MTOT    (T_STEPS * BATCH)   // 65536
#define BHD     (BATCH * HDIM)

// ---- device-global scratch (no allocs allowed) ----
__device__ float          g_xproj[(size_t)MTOT * G4];    // 512 MB
__device__ unsigned short g_Ah16[(size_t)MTOT * IDIM];   // 64 MB (A fp16)
__device__ unsigned short g_Wh16[(size_t)G4 * IDIM];     // 2 MB (W_ih fp16)
__device__ unsigned short g_hpackH[2 * BHD];             // double-buffered fp16 h
__device__ unsigned int   g_barF[4 * 8 * 32];            // per-(group,K-slice) flags
__device__ unsigned int   g_done;

__device__ __forceinline__ float sigf(float x) {
    return __fdividef(1.0f, 1.0f + __expf(-x));
}

// ---------------- helpers ----------------
__device__ __forceinline__ uint32_t smem_u32(const void* p) {
    uint32_t a;
    asm("{ .reg .u64 t; cvta.to.shared.u64 t, %1; cvt.u32.u64 %0, t; }"
        : "=r"(a) : "l"(p));
    return a;
}
__device__ __forceinline__ void ldm4(uint32_t* r, uint32_t addr) {
    asm volatile("ldmatrix.sync.aligned.m8n8.x4.shared.b16 {%0,%1,%2,%3}, [%4];"
                 : "=r"(r[0]), "=r"(r[1]), "=r"(r[2]), "=r"(r[3]) : "r"(addr));
}
__device__ __forceinline__ void mma16816h(float* d, const uint32_t* a,
                                          uint32_t b0, uint32_t b1) {
    asm volatile(
        "mma.sync.aligned.m16n8k16.row.col.f32.f16.f16.f32 "
        "{%0,%1,%2,%3}, {%4,%5,%6,%7}, {%8,%9}, {%0,%1,%2,%3};"
        : "+f"(d[0]), "+f"(d[1]), "+f"(d[2]), "+f"(d[3])
        : "r"(a[0]), "r"(a[1]), "r"(a[2]), "r"(a[3]), "r"(b0), "r"(b1));
}
// plain fp16 convert of float4 -> packed uint2
__device__ __forceinline__ uint2 cvt4h(const float4 v) {
    __half2 p0 = __floats2half2_rn(v.x, v.y);
    __half2 p1 = __floats2half2_rn(v.z, v.w);
    uint2 r;
    r.x = *reinterpret_cast<const uint32_t*>(&p0);
    r.y = *reinterpret_cast<const uint32_t*>(&p1);
    return r;
}

// ---------------------------------------------------------------------------
// Kernel 0: one-shot conversions. A -> fp16; W_ih -> fp16.
// ---------------------------------------------------------------------------
__global__ void __launch_bounds__(256) conv_kernel(
    const float* __restrict__ A, const float* __restrict__ W)
{
    size_t i = (size_t)blockIdx.x * 256 + threadIdx.x;
    size_t base = i * 8;
    if (base < (size_t)MTOT * IDIM) {
        float4 v0 = *(const float4*)(A + base);
        float4 v1 = *(const float4*)(A + base + 4);
        uint2 a = cvt4h(v0), b = cvt4h(v1);
        *(uint4*)(g_Ah16 + base) = make_uint4(a.x, a.y, b.x, b.y);
    }
    if (base < (size_t)G4 * IDIM) {
        float4 w0 = *(const float4*)(W + base);
        float4 w1 = *(const float4*)(W + base + 4);
        uint2 h0 = cvt4h(w0), h1 = cvt4h(w1);
        *(uint4*)(g_Wh16 + base) = make_uint4(h0.x, h0.y, h1.x, h1.y);
    }
}

// ---------------------------------------------------------------------------
// Kernel 1: x_proj via single-term fp16 HMMA. D = A*W + bias.
// Tile 128x128, 8 warps 4(M)x2(N), K chunks of 32.
// ---------------------------------------------------------------------------
#define XS_ROW   80
#define XS_BUF   (128 * XS_ROW)
__global__ void __launch_bounds__(256, 1) xproj_mma_kernel(
    const float* __restrict__ bih, const float* __restrict__ bhh)
{
    __shared__ __align__(16) char sA [XS_BUF];
    __shared__ __align__(16) char sWH[XS_BUF];
    __shared__ float sBias[128];

    const int tid = threadIdx.x;
    const int n0 = blockIdx.x * 128;
    const int m0 = blockIdx.y * 128;
    const int lane = tid & 31, wid = tid >> 5;
    const int wm = wid >> 1, wn = wid & 1;

    if (tid < 128) sBias[tid] = bih[n0 + tid] + bhh[n0 + tid];

    const int srow = tid >> 3;
    const int sc4  = (tid & 7) << 2;
    const unsigned short* agp = g_Ah16 + (size_t)(m0 + srow) * IDIM + sc4;
    const unsigned short* whp = g_Wh16 + (size_t)(n0 + srow) * IDIM + sc4;

    const int lr = lane & 7, sel = lane >> 3;
    const int koff2 = ((sel >> 1) * 8) * 2;
    const uint32_t aB = smem_u32(sA)  + (uint32_t)(wm * 32 + (sel & 1) * 8 + lr) * XS_ROW + koff2;
    const uint32_t bH = smem_u32(sWH) + (uint32_t)(wn * 64 + (sel & 1) * 8 + lr) * XS_ROW + koff2;

    float d[2][8][4];
#pragma unroll
    for (int i = 0; i < 2; i++)
#pragma unroll
        for (int j = 0; j < 8; j++)
#pragma unroll
            for (int q = 0; q < 4; q++) d[i][j][q] = 0.0f;

    uint2 pfA[4], pfWh[4];
#pragma unroll
    for (int i = 0; i < 4; i++) {
        pfA[i]  = *(const uint2*)(agp + (size_t)i * 32 * IDIM);
        pfWh[i] = *(const uint2*)(whp + (size_t)i * 32 * IDIM);
    }

    for (int kc = 0; kc < 16; kc++) {
#pragma unroll
        for (int i = 0; i < 4; i++) {
            int row = srow + i * 32;
            *(uint2*)(sA  + row * XS_ROW + sc4 * 2) = pfA[i];
            *(uint2*)(sWH + row * XS_ROW + sc4 * 2) = pfWh[i];
        }
        __syncthreads();

        if (kc < 15) {
            const unsigned short* an = agp + (kc + 1) * 32;
            const unsigned short* hn = whp + (kc + 1) * 32;
#pragma unroll
            for (int i = 0; i < 4; i++) {
                pfA[i]  = *(const uint2*)(an + (size_t)i * 32 * IDIM);
                pfWh[i] = *(const uint2*)(hn + (size_t)i * 32 * IDIM);
            }
        }

#pragma unroll
        for (int k16 = 0; k16 < 2; k16++) {
            const uint32_t ko = (uint32_t)(k16 * 32);
            uint32_t a0[4], a1[4];
            ldm4(a0, aB + ko);
            ldm4(a1, aB + ko + 16 * XS_ROW);
#pragma unroll
            for (int bnp = 0; bnp < 4; bnp++) {
                uint32_t bh[4];
                ldm4(bh, bH + ko + (uint32_t)(bnp * 16) * XS_ROW);
                mma16816h(d[0][2 * bnp],     a0, bh[0], bh[2]);
                mma16816h(d[0][2 * bnp + 1], a0, bh[1], bh[3]);
                mma16816h(d[1][2 * bnp],     a1, bh[0], bh[2]);
                mma16816h(d[1][2 * bnp + 1], a1, bh[1], bh[3]);
            }
        }
        __syncthreads();
    }

    const int erow = m0 + wm * 32 + (lane >> 2);
    const int ecol = wn * 64 + (lane & 3) * 2;
#pragma unroll
    for (int am = 0; am < 2; am++) {
#pragma unroll
        for (int bn = 0; bn < 8; bn++) {
            int col = ecol + bn * 8;
            float b0 = sBias[col], b1 = sBias[col + 1];
            float* p0 = g_xproj + (size_t)(erow + am * 16) * G4 + n0 + col;
            float* p1 = p0 + 8 * G4;
            *(float2*)p0 = make_float2(d[am][bn][0] + b0, d[am][bn][1] + b1);
            *(float2*)p1 = make_float2(d[am][bn][2] + b0, d[am][bn][3] + b1);
        }
    }
}

// ---------------------------------------------------------------------------
// Kernel 2: recurrence, single-term fp16 (W fp16, h fp16).
// Slice flags + warp-pair role split + bar.arrive partials join (as R13).
// ---------------------------------------------------------------------------
#define OFF_WHI  0
#define OFF_P9A  0
#define OFF_P9B  36864
#define OFF_HHI  133120
#define OFF_XP   166400
#define R_SMEM   174592

__global__ void __launch_bounds__(512, 1) recur_mma_kernel(
    const float* __restrict__ h0, const float* __restrict__ c0,
    const float* __restrict__ Whh, float* __restrict__ out)
{
    extern __shared__ char sm[];

    const int tid  = threadIdx.x;
    const int lane = tid & 31, wid = tid >> 5;
    const int kw = wid >> 1;
    const int nw = wid & 1;
    const int cg = blockIdx.x;
    const int j0 = cg * 16;
    const int B0 = blockIdx.y * 16;
    const int grp = blockIdx.y;
    unsigned int* flagR = &g_barF[(grp * 8 + kw) * 32];
    unsigned int* flagW = &g_barF[(grp * 8 + (cg >> 2)) * 32];

    // ---- convert W_hh slice to fp16 in SMEM (init only) ----
#pragma unroll 4
    for (int i = 0; i < 16; i++) {
        int idx = tid + i * 512;
        int row = idx >> 7;
        int f4  = (idx & 127) << 2;
        int gate = row >> 4, jj = row & 15;
        float4 v = *(const float4*)(Whh
                      + (size_t)(gate * HDIM + j0 + jj) * HDIM + f4);
        *(uint2*)(sm + OFF_WHI + row * 1040 + f4 * 2) = cvt4h(v);
    }
    __syncthreads();

    // ---- load B (W) fragments into registers (once) ----
    const int lr = lane & 7, sel = lane >> 3;
    uint32_t BH[4][2][4];
#pragma unroll
    for (int ks = 0; ks < 4; ks++)
#pragma unroll
        for (int p = 0; p < 2; p++) {
            uint32_t off = (uint32_t)(nw * 32 + p * 16 + (sel & 1) * 8 + lr) * 1040u
                         + (uint32_t)((sel >> 1) * 16)
                         + (uint32_t)(kw * 128 + ks * 32);
            ldm4(BH[ks][p], smem_u32(sm + OFF_WHI) + off);
        }

    const uint32_t aRowOff = (uint32_t)((sel & 1) * 8 + lr) * 1040u
                           + (uint32_t)((sel >> 1) * 16)
                           + (uint32_t)(kw * 128);
    const uint32_t aHiB = smem_u32(sm + OFF_HHI) + aRowOff;

    float* xp_s = (float*)(sm + OFF_XP);

    float creg = 0.0f;
    int cb_ = 0, cjj_ = 0;
    int xb = 0, xg = 0, xf = 0;

    if (nw == 0) {
        int ct = kw * 32 + lane;
        cb_ = ct >> 4; cjj_ = ct & 15;
        creg = c0[(size_t)(B0 + cb_) * HDIM + j0 + cjj_];
        float hv = h0[(size_t)(B0 + cb_) * HDIM + j0 + cjj_];
        g_hpackH[(size_t)(B0 + cb_) * HDIM + j0 + cjj_]
            = __half_as_ushort(__float2half_rn(hv));
        __syncwarp();
        if (lane == 0) {
            asm volatile("red.release.gpu.global.add.u32 [%0], %1;"
                         :: "l"(flagW), "r"(1u) : "memory");
        }
    } else {
        int ot = kw * 32 + lane;
        xb = ot >> 4; int q = ot & 15; xg = q >> 2; xf = q & 3;
        float4 xv = *(const float4*)(g_xproj
                + ((size_t)(T_STEPS - 1) * BATCH + B0 + xb) * G4
                + xg * HDIM + j0 + xf * 4);
        *(float4*)(xp_s + 1024 + xb * 64 + xg * 16 + xf * 4) = xv;
        unsigned v;
        do {
            asm volatile("ld.acquire.gpu.global.u32 %0, [%1];"
                         : "=r"(v) : "l"(flagR) : "memory");
        } while (v < 32u);
        uint4 pv[4];
#pragma unroll
        for (int j = 0; j < 4; j++) {
            int idx = j * 32 + lane;
            int r = idx >> 3, c16 = (idx & 7) * 8;
            pv[j] = *(const uint4*)(g_hpackH + (size_t)(B0 + r) * HDIM
                                    + kw * 64 + c16);
        }
#pragma unroll
        for (int j = 0; j < 4; j++) {
            int idx = j * 32 + lane;
            int r = idx >> 3, c16 = (idx & 7) * 8;
            *(uint4*)(sm + OFF_HHI + r * 1040 + (kw * 64 + c16) * 2) = pv[j];
        }
    }
    __syncthreads();

    for (int t = T_STEPS - 1; t >= 0; t--) {
        asm volatile("bar.sync %0, 64;" :: "r"(1 + kw) : "memory");

        uint32_t ah[4][4];
#pragma unroll
        for (int ks = 0; ks < 4; ks++)
            ldm4(ah[ks], aHiB + (uint32_t)(ks * 32));
        float acc[4][4];
#pragma unroll
        for (int q = 0; q < 4; q++)
#pragma unroll
            for (int i = 0; i < 4; i++) acc[q][i] = 0.0f;
#pragma unroll
        for (int ks = 0; ks < 4; ks++) {
#pragma unroll
            for (int q = 0; q < 4; q++) {
                const int p = q >> 1, hh = q & 1;
                mma16816h(acc[q], ah[ks], BH[ks][p][hh], BH[ks][p][hh + 2]);
            }
        }
        float* p9 = (float*)(sm + ((t & 1) ? OFF_P9B : OFF_P9A));
        {
            const int r = lane >> 2;
            const int c2 = (lane & 3) * 2;
            float* base = p9 + kw * 1092;
#pragma unroll
            for (int q = 0; q < 4; q++) {
                int cc = nw * 32 + q * 8 + c2;
                *(float2*)(base + r * 68 + cc)       = make_float2(acc[q][0], acc[q][1]);
                *(float2*)(base + (r + 8) * 68 + cc) = make_float2(acc[q][2], acc[q][3]);
            }
        }

        if (nw == 0) {
            asm volatile("bar.sync 9, 512;" ::: "memory");
            const float* xps = xp_s + (t & 1) * 1024;
            float pre[4];
#pragma unroll
            for (int g = 0; g < 4; g++) {
                int off = cb_ * 68 + g * 16 + cjj_;
                float s0 = p9[off]            + p9[1092 + off];
                float s1 = p9[2 * 1092 + off] + p9[3 * 1092 + off];
                float s2 = p9[4 * 1092 + off] + p9[5 * 1092 + off];
                float s3 = p9[6 * 1092 + off] + p9[7 * 1092 + off];
                pre[g] = ((s0 + s1) + (s2 + s3)) + xps[cb_ * 64 + g * 16 + cjj_];
            }
            float gi = sigf(pre[0]);
            float gf = sigf(pre[1]);
            float gz = sigf(pre[2]);
            float go = sigf(pre[3]);
            float cn = gf * creg + gz - gi;
            creg = cn;
            float hn = sigf(cn) - go;
            g_hpackH[(size_t)(t & 1) * BHD + (size_t)(B0 + cb_) * HDIM + j0 + cjj_]
                = __half_as_ushort(__float2half_rn(hn));
            __syncwarp();
            if (lane == 0 && t > 0) {
                asm volatile("red.release.gpu.global.add.u32 [%0], %1;"
                             :: "l"(flagW), "r"(1u) : "memory");
            }
            out[(size_t)t * BHD + (size_t)(B0 + cb_) * HDIM + j0 + cjj_] = hn;
            if (t == 0) {
                const size_t base = (size_t)T_STEPS * BHD;
                out[base + (size_t)(B0 + cb_) * HDIM + j0 + cjj_] = hn;
                out[base + BHD + (size_t)(B0 + cb_) * HDIM + j0 + cjj_] = cn;
            }
        } else {
            asm volatile("bar.arrive 9, 512;" ::: "memory");
            if (t > 0) {
                float4 xv = *(const float4*)(g_xproj
                        + ((size_t)(t - 1) * BATCH + B0 + xb) * G4
                        + xg * HDIM + j0 + xf * 4);
                unsigned target = (unsigned)(T_STEPS - t + 1) * 32u;
                unsigned v;
                do {
                    asm volatile("ld.acquire.gpu.global.u32 %0, [%1];"
                                 : "=r"(v) : "l"(flagR) : "memory");
                } while (v < target);

                const unsigned short* hb = g_hpackH + (size_t)(t & 1) * BHD;
                uint4 pv[4];
#pragma unroll
                for (int j = 0; j < 4; j++) {
                    int idx = j * 32 + lane;
                    int r = idx >> 3, c16 = (idx & 7) * 8;
                    pv[j] = *(const uint4*)(hb + (size_t)(B0 + r) * HDIM
                                            + kw * 64 + c16);
                }
#pragma unroll
                for (int j = 0; j < 4; j++) {
                    int idx = j * 32 + lane;
                    int r = idx >> 3, c16 = (idx & 7) * 8;
                    *(uint4*)(sm + OFF_HHI + r * 1040 + (kw * 64 + c16) * 2) = pv[j];
                }
                *(float4*)(xp_s + ((t - 1) & 1) * 1024 + xb * 64 + xg * 16 + xf * 4) = xv;
            }
        }
    }

    __syncthreads();
    if (tid == 0) {
        unsigned v = atomicAdd(&g_done, 1u);
        if (v == 127u) {
            for (int i = 0; i < 32; i++)
                atomicExch(&g_barF[i * 32], 0u);
            atomicExch(&g_done, 0u);
        }
    }
}

// ---------------------------------------------------------------------------
extern "C" void kernel_launch(void* const* d_in, const int* in_sizes, int n_in,
                              void* d_out, int out_size)
{
    const float* input = (const float*)d_in[0];
    const float* h0    = (const float*)d_in[1];
    const float* c0    = (const float*)d_in[2];
    const float* Wih   = (const float*)d_in[3];
    const float* Whh   = (const float*)d_in[4];
    const float* bih   = (const float*)d_in[5];
    const float* bhh   = (const float*)d_in[6];
    float* out = (float*)d_out;

    static int configured = 0;
    if (!configured) {
        cudaFuncSetAttribute(recur_mma_kernel,
                             cudaFuncAttributeMaxDynamicSharedMemorySize,
                             R_SMEM);
        configured = 1;
    }

    conv_kernel<<<(int)(((size_t)MTOT * IDIM / 8 + 255) / 256), 256>>>(input, Wih);
    xproj_mma_kernel<<<dim3(G4 / 128, MTOT / 128), 256>>>(bih, bhh);
    recur_mma_kernel<<<dim3(HDIM / 16, BATCH / 16), 512, R_SMEM>>>(
        h0, c0, Whh, out);
}

// round 16
// speedup vs baseline: 2.4366x; 1.2864x over previous
#include <cuda_runtime.h>
#include <cuda_bf16.h>
#include <cuda_fp16.h>
#include <math.h>
#include <stdint.h>

#define T_STEPS 1024
#define BATCH   64
#define IDIM    512
#define HDIM    512
#define G4      2048   // 4*H
#define MTOT    (T_STEPS * BATCH)   // 65536
#define BHD     (BATCH * HDIM)

// ---- device-global scratch (no allocs allowed) ----
__device__ float          g_xproj[(size_t)MTOT * G4];    // 512 MB
__device__ unsigned short g_Ah16[(size_t)MTOT * IDIM];   // 64 MB (A fp16)
__device__ unsigned short g_Wh16[(size_t)G4 * IDIM];     // 2 MB (W_ih fp16)
__device__ uint32_t       g_h32[2 * BHD];                // tagged fp16 h (dbl-buf)
__device__ unsigned int   g_epoch;                       // bumped once per launch

__device__ __forceinline__ float sigf(float x) {
    return __fdividef(1.0f, 1.0f + __expf(-x));
}

// ---------------- helpers ----------------
__device__ __forceinline__ uint32_t smem_u32(const void* p) {
    uint32_t a;
    asm("{ .reg .u64 t; cvta.to.shared.u64 t, %1; cvt.u32.u64 %0, t; }"
        : "=r"(a) : "l"(p));
    return a;
}
__device__ __forceinline__ uint32_t prmt(uint32_t a, uint32_t b, uint32_t s) {
    uint32_t r;
    asm("prmt.b32 %0, %1, %2, %3;" : "=r"(r) : "r"(a), "r"(b), "r"(s));
    return r;
}
__device__ __forceinline__ void ldm4(uint32_t* r, uint32_t addr) {
    asm volatile("ldmatrix.sync.aligned.m8n8.x4.shared.b16 {%0,%1,%2,%3}, [%4];"
                 : "=r"(r[0]), "=r"(r[1]), "=r"(r[2]), "=r"(r[3]) : "r"(addr));
}
__device__ __forceinline__ void mma16816h(float* d, const uint32_t* a,
                                          uint32_t b0, uint32_t b1) {
    asm volatile(
        "mma.sync.aligned.m16n8k16.row.col.f32.f16.f16.f32 "
        "{%0,%1,%2,%3}, {%4,%5,%6,%7}, {%8,%9}, {%0,%1,%2,%3};"
        : "+f"(d[0]), "+f"(d[1]), "+f"(d[2]), "+f"(d[3])
        : "r"(a[0]), "r"(a[1]), "r"(a[2]), "r"(a[3]), "r"(b0), "r"(b1));
}
__device__ __forceinline__ uint2 cvt4h(const float4 v) {
    __half2 p0 = __floats2half2_rn(v.x, v.y);
    __half2 p1 = __floats2half2_rn(v.z, v.w);
    uint2 r;
    r.x = *reinterpret_cast<const uint32_t*>(&p0);
    r.y = *reinterpret_cast<const uint32_t*>(&p1);
    return r;
}

// ---------------------------------------------------------------------------
// Kernel 0: one-shot conversions + epoch bump.
// ---------------------------------------------------------------------------
__global__ void __launch_bounds__(256) conv_kernel(
    const float* __restrict__ A, const float* __restrict__ W)
{
    if (blockIdx.x == 0 && threadIdx.x == 0) g_epoch = g_epoch + 1u;
    size_t i = (size_t)blockIdx.x * 256 + threadIdx.x;
    size_t base = i * 8;
    if (base < (size_t)MTOT * IDIM) {
        float4 v0 = *(const float4*)(A + base);
        float4 v1 = *(const float4*)(A + base + 4);
        uint2 a = cvt4h(v0), b = cvt4h(v1);
        *(uint4*)(g_Ah16 + base) = make_uint4(a.x, a.y, b.x, b.y);
    }
    if (base < (size_t)G4 * IDIM) {
        float4 w0 = *(const float4*)(W + base);
        float4 w1 = *(const float4*)(W + base + 4);
        uint2 h0 = cvt4h(w0), h1 = cvt4h(w1);
        *(uint4*)(g_Wh16 + base) = make_uint4(h0.x, h0.y, h1.x, h1.y);
    }
}

// ---------------------------------------------------------------------------
// Kernel 1: x_proj via single-term fp16 HMMA (UNCHANGED from R15, passing).
// ---------------------------------------------------------------------------
#define XS_ROW   80
#define XS_BUF   (128 * XS_ROW)
__global__ void __launch_bounds__(256, 1) xproj_mma_kernel(
    const float* __restrict__ bih, const float* __restrict__ bhh)
{
    __shared__ __align__(16) char sA [XS_BUF];
    __shared__ __align__(16) char sWH[XS_BUF];
    __shared__ float sBias[128];

    const int tid = threadIdx.x;
    const int n0 = blockIdx.x * 128;
    const int m0 = blockIdx.y * 128;
    const int lane = tid & 31, wid = tid >> 5;
    const int wm = wid >> 1, wn = wid & 1;

    if (tid < 128) sBias[tid] = bih[n0 + tid] + bhh[n0 + tid];

    const int srow = tid >> 3;
    const int sc4  = (tid & 7) << 2;
    const unsigned short* agp = g_Ah16 + (size_t)(m0 + srow) * IDIM + sc4;
    const unsigned short* whp = g_Wh16 + (size_t)(n0 + srow) * IDIM + sc4;

    const int lr = lane & 7, sel = lane >> 3;
    const int koff2 = ((sel >> 1) * 8) * 2;
    const uint32_t aB = smem_u32(sA)  + (uint32_t)(wm * 32 + (sel & 1) * 8 + lr) * XS_ROW + koff2;
    const uint32_t bH = smem_u32(sWH) + (uint32_t)(wn * 64 + (sel & 1) * 8 + lr) * XS_ROW + koff2;

    float d[2][8][4];
#pragma unroll
    for (int i = 0; i < 2; i++)
#pragma unroll
        for (int j = 0; j < 8; j++)
#pragma unroll
            for (int q = 0; q < 4; q++) d[i][j][q] = 0.0f;

    uint2 pfA[4], pfWh[4];
#pragma unroll
    for (int i = 0; i < 4; i++) {
        pfA[i]  = *(const uint2*)(agp + (size_t)i * 32 * IDIM);
        pfWh[i] = *(const uint2*)(whp + (size_t)i * 32 * IDIM);
    }

    for (int kc = 0; kc < 16; kc++) {
#pragma unroll
        for (int i = 0; i < 4; i++) {
            int row = srow + i * 32;
            *(uint2*)(sA  + row * XS_ROW + sc4 * 2) = pfA[i];
            *(uint2*)(sWH + row * XS_ROW + sc4 * 2) = pfWh[i];
        }
        __syncthreads();

        if (kc < 15) {
            const unsigned short* an = agp + (kc + 1) * 32;
            const unsigned short* hn = whp + (kc + 1) * 32;
#pragma unroll
            for (int i = 0; i < 4; i++) {
                pfA[i]  = *(const uint2*)(an + (size_t)i * 32 * IDIM);
                pfWh[i] = *(const uint2*)(hn + (size_t)i * 32 * IDIM);
            }
        }

#pragma unroll
        for (int k16 = 0; k16 < 2; k16++) {
            const uint32_t ko = (uint32_t)(k16 * 32);
            uint32_t a0[4], a1[4];
            ldm4(a0, aB + ko);
            ldm4(a1, aB + ko + 16 * XS_ROW);
#pragma unroll
            for (int bnp = 0; bnp < 4; bnp++) {
                uint32_t bh[4];
                ldm4(bh, bH + ko + (uint32_t)(bnp * 16) * XS_ROW);
                mma16816h(d[0][2 * bnp],     a0, bh[0], bh[2]);
                mma16816h(d[0][2 * bnp + 1], a0, bh[1], bh[3]);
                mma16816h(d[1][2 * bnp],     a1, bh[0], bh[2]);
                mma16816h(d[1][2 * bnp + 1], a1, bh[1], bh[3]);
            }
        }
        __syncthreads();
    }

    const int erow = m0 + wm * 32 + (lane >> 2);
    const int ecol = wn * 64 + (lane & 3) * 2;
#pragma unroll
    for (int am = 0; am < 2; am++) {
#pragma unroll
        for (int bn = 0; bn < 8; bn++) {
            int col = ecol + bn * 8;
            float b0 = sBias[col], b1 = sBias[col + 1];
            float* p0 = g_xproj + (size_t)(erow + am * 16) * G4 + n0 + col;
            float* p1 = p0 + 8 * G4;
            *(float2*)p0 = make_float2(d[am][bn][0] + b0, d[am][bn][1] + b1);
            *(float2*)p1 = make_float2(d[am][bn][2] + b0, d[am][bn][3] + b1);
        }
    }
}

// ---------------------------------------------------------------------------
// Kernel 2: recurrence with tagged-word h exchange (no flags, 1 L2 RT/step).
// ---------------------------------------------------------------------------
#define OFF_WHI  0
#define OFF_P9A  0
#define OFF_P9B  36864
#define OFF_HHI  133120
#define OFF_XP   166400
#define R_SMEM   174592

// Poll a 16x64 h slice (tagged u32 words) until all tags == tt, then pack the
// fp16 payloads into the SMEM A plane. Two phases of 4 x uint4 per lane.
__device__ __forceinline__ void stage_slice(char* sm, int lane, int kw, int B0,
                                            const uint32_t* hb, uint32_t tt)
{
#pragma unroll
    for (int ph = 0; ph < 2; ph++) {
        uint4 pv[4];
        unsigned ok;
        do {
            ok = 1u;
#pragma unroll
            for (int j = 0; j < 4; j++) {
                int idx = (ph * 4 + j) * 32 + lane;
                int r = idx >> 4, c4 = (idx & 15) * 4;
                const uint32_t* p = hb + (size_t)(B0 + r) * HDIM + kw * 64 + c4;
                asm volatile("ld.relaxed.gpu.global.v4.u32 {%0,%1,%2,%3}, [%4];"
                             : "=r"(pv[j].x), "=r"(pv[j].y),
                               "=r"(pv[j].z), "=r"(pv[j].w)
                             : "l"(p));
                ok &= (unsigned)((pv[j].x >> 16) == tt);
                ok &= (unsigned)((pv[j].y >> 16) == tt);
                ok &= (unsigned)((pv[j].z >> 16) == tt);
                ok &= (unsigned)((pv[j].w >> 16) == tt);
            }
        } while (!__all_sync(0xffffffffu, ok));
#pragma unroll
        for (int j = 0; j < 4; j++) {
            int idx = (ph * 4 + j) * 32 + lane;
            int r = idx >> 4, c4 = (idx & 15) * 4;
            uint2 pk;
            pk.x = prmt(pv[j].x, pv[j].y, 0x5410);
            pk.y = prmt(pv[j].z, pv[j].w, 0x5410);
            *(uint2*)(sm + OFF_HHI + r * 1040 + (kw * 64 + c4) * 2) = pk;
        }
    }
}

__global__ void __launch_bounds__(512, 1) recur_mma_kernel(
    const float* __restrict__ h0, const float* __restrict__ c0,
    const float* __restrict__ Whh, float* __restrict__ out)
{
    extern __shared__ char sm[];

    const int tid  = threadIdx.x;
    const int lane = tid & 31, wid = tid >> 5;
    const int kw = wid >> 1;
    const int nw = wid & 1;
    const int cg = blockIdx.x;
    const int j0 = cg * 16;
    const int B0 = blockIdx.y * 16;
    const uint32_t tagb = (g_epoch & 31u) << 11;   // 5-bit epoch | 11-bit t

    // ---- convert W_hh slice to fp16 in SMEM (init only) ----
#pragma unroll 4
    for (int i = 0; i < 16; i++) {
        int idx = tid + i * 512;
        int row = idx >> 7;
        int f4  = (idx & 127) << 2;
        int gate = row >> 4, jj = row & 15;
        float4 v = *(const float4*)(Whh
                      + (size_t)(gate * HDIM + j0 + jj) * HDIM + f4);
        *(uint2*)(sm + OFF_WHI + row * 1040 + f4 * 2) = cvt4h(v);
    }
    __syncthreads();

    // ---- load B (W) fragments into registers (once) ----
    const int lr = lane & 7, sel = lane >> 3;
    uint32_t BH[4][2][4];
#pragma unroll
    for (int ks = 0; ks < 4; ks++)
#pragma unroll
        for (int p = 0; p < 2; p++) {
            uint32_t off = (uint32_t)(nw * 32 + p * 16 + (sel & 1) * 8 + lr) * 1040u
                         + (uint32_t)((sel >> 1) * 16)
                         + (uint32_t)(kw * 128 + ks * 32);
            ldm4(BH[ks][p], smem_u32(sm + OFF_WHI) + off);
        }

    const uint32_t aRowOff = (uint32_t)((sel & 1) * 8 + lr) * 1040u
                           + (uint32_t)((sel >> 1) * 16)
                           + (uint32_t)(kw * 128);
    const uint32_t aHiB = smem_u32(sm + OFF_HHI) + aRowOff;

    float* xp_s = (float*)(sm + OFF_XP);

    float creg = 0.0f;
    int cb_ = 0, cjj_ = 0;
    int xb = 0, xg = 0, xf = 0;

    if (nw == 0) {
        int ct = kw * 32 + lane;
        cb_ = ct >> 4; cjj_ = ct & 15;
        creg = c0[(size_t)(B0 + cb_) * HDIM + j0 + cjj_];
        float hv = h0[(size_t)(B0 + cb_) * HDIM + j0 + cjj_];
        uint32_t hw = ((tagb | 1024u) << 16)
                    | (uint32_t)__half_as_ushort(__float2half_rn(hv));
        uint32_t* hp = g_h32 + (size_t)(B0 + cb_) * HDIM + j0 + cjj_; // buf 0
        asm volatile("st.relaxed.gpu.global.u32 [%0], %1;"
                     :: "l"(hp), "r"(hw) : "memory");
    } else {
        int ot = kw * 32 + lane;
        xb = ot >> 4; int q = ot & 15; xg = q >> 2; xf = q & 3;
        float4 xv = *(const float4*)(g_xproj
                + ((size_t)(T_STEPS - 1) * BATCH + B0 + xb) * G4
                + xg * HDIM + j0 + xf * 4);
        *(float4*)(xp_s + 1024 + xb * 64 + xg * 16 + xf * 4) = xv;
        // stage h0 (tag = 1024, buffer 0)
        stage_slice(sm, lane, kw, B0, g_h32, tagb | 1024u);
    }
    __syncthreads();

    for (int t = T_STEPS - 1; t >= 0; t--) {
        asm volatile("bar.sync %0, 64;" :: "r"(1 + kw) : "memory");

        uint32_t ah[4][4];
#pragma unroll
        for (int ks = 0; ks < 4; ks++)
            ldm4(ah[ks], aHiB + (uint32_t)(ks * 32));
        float acc[4][4];
#pragma unroll
        for (int q = 0; q < 4; q++)
#pragma unroll
            for (int i = 0; i < 4; i++) acc[q][i] = 0.0f;
#pragma unroll
        for (int ks = 0; ks < 4; ks++) {
#pragma unroll
            for (int q = 0; q < 4; q++) {
                const int p = q >> 1, hh = q & 1;
                mma16816h(acc[q], ah[ks], BH[ks][p][hh], BH[ks][p][hh + 2]);
            }
        }
        float* p9 = (float*)(sm + ((t & 1) ? OFF_P9B : OFF_P9A));
        {
            const int r = lane >> 2;
            const int c2 = (lane & 3) * 2;
            float* base = p9 + kw * 1092;
#pragma unroll
            for (int q = 0; q < 4; q++) {
                int cc = nw * 32 + q * 8 + c2;
                *(float2*)(base + r * 68 + cc)       = make_float2(acc[q][0], acc[q][1]);
                *(float2*)(base + (r + 8) * 68 + cc) = make_float2(acc[q][2], acc[q][3]);
            }
        }

        if (nw == 0) {
            asm volatile("bar.sync 9, 512;" ::: "memory");
            const float* xps = xp_s + (t & 1) * 1024;
            float pre[4];
#pragma unroll
            for (int g = 0; g < 4; g++) {
                int off = cb_ * 68 + g * 16 + cjj_;
                float s0 = p9[off]            + p9[1092 + off];
                float s1 = p9[2 * 1092 + off] + p9[3 * 1092 + off];
                float s2 = p9[4 * 1092 + off] + p9[5 * 1092 + off];
                float s3 = p9[6 * 1092 + off] + p9[7 * 1092 + off];
                pre[g] = ((s0 + s1) + (s2 + s3)) + xps[cb_ * 64 + g * 16 + cjj_];
            }
            float gi = sigf(pre[0]);
            float gf = sigf(pre[1]);
            float gz = sigf(pre[2]);
            float go = sigf(pre[3]);
            float cn = gf * creg + gz - gi;
            creg = cn;
            float hn = sigf(cn) - go;
            // publish tagged h word first (single L2 RT hand-off)
            uint32_t hw = ((tagb | (uint32_t)t) << 16)
                        | (uint32_t)__half_as_ushort(__float2half_rn(hn));
            uint32_t* hp = g_h32 + (size_t)(t & 1) * BHD
                         + (size_t)(B0 + cb_) * HDIM + j0 + cjj_;
            asm volatile("st.relaxed.gpu.global.u32 [%0], %1;"
                         :: "l"(hp), "r"(hw) : "memory");
            out[(size_t)t * BHD + (size_t)(B0 + cb_) * HDIM + j0 + cjj_] = hn;
            if (t == 0) {
                const size_t base = (size_t)T_STEPS * BHD;
                out[base + (size_t)(B0 + cb_) * HDIM + j0 + cjj_] = hn;
                out[base + BHD + (size_t)(B0 + cb_) * HDIM + j0 + cjj_] = cn;
            }
        } else {
            asm volatile("bar.arrive 9, 512;" ::: "memory");
            if (t > 0) {
                float4 xv = *(const float4*)(g_xproj
                        + ((size_t)(t - 1) * BATCH + B0 + xb) * G4
                        + xg * HDIM + j0 + xf * 4);
                // stage h(t) (tag t, buffer t&1); poll returns the data
                stage_slice(sm, lane, kw, B0,
                            g_h32 + (size_t)(t & 1) * BHD,
                            tagb | (uint32_t)t);
                *(float4*)(xp_s + ((t - 1) & 1) * 1024 + xb * 64 + xg * 16 + xf * 4) = xv;
            }
        }
    }
}

// ---------------------------------------------------------------------------
extern "C" void kernel_launch(void* const* d_in, const int* in_sizes, int n_in,
                              void* d_out, int out_size)
{
    const float* input = (const float*)d_in[0];
    const float* h0    = (const float*)d_in[1];
    const float* c0    = (const float*)d_in[2];
    const float* Wih   = (const float*)d_in[3];
    const float* Whh   = (const float*)d_in[4];
    const float* bih   = (const float*)d_in[5];
    const float* bhh   = (const float*)d_in[6];
    float* out = (float*)d_out;

    static int configured = 0;
    if (!configured) {
        cudaFuncSetAttribute(recur_mma_kernel,
                             cudaFuncAttributeMaxDynamicSharedMemorySize,
                             R_SMEM);
        configured = 1;
    }

    conv_kernel<<<(int)(((size_t)MTOT * IDIM / 8 + 255) / 256), 256>>>(input, Wih);
    xproj_mma_kernel<<<dim3(G4 / 128, MTOT / 128), 256>>>(bih, bhh);
    recur_mma_kernel<<<dim3(HDIM / 16, BATCH / 16), 512, R_SMEM>>>(
        h0, c0, Whh, out);
}

// round 17
// speedup vs baseline: 2.4742x; 1.0154x over previous
#include <cuda_runtime.h>
#include <cuda_bf16.h>
#include <cuda_fp16.h>
#include <math.h>
#include <stdint.h>

#define T_STEPS 1024
#define BATCH   64
#define IDIM    512
#define HDIM    512
#define G4      2048   // 4*H
#define MTOT    (T_STEPS * BATCH)   // 65536
#define BHD     (BATCH * HDIM)

// ---- device-global scratch (no allocs allowed) ----
__device__ unsigned short g_Ah16[(size_t)MTOT * IDIM];   // 64 MB (A fp16)
__device__ unsigned short g_Wh16[(size_t)G4 * IDIM];     // 2 MB (W_ih fp16)
__device__ uint32_t       g_h32[2 * BHD];                // tagged fp16 h (dbl-buf)
__device__ unsigned int   g_epoch;                       // bumped once per launch

__device__ __forceinline__ float sigf(float x) {
    return __fdividef(1.0f, 1.0f + __expf(-x));
}

// ---------------- helpers ----------------
__device__ __forceinline__ uint32_t smem_u32(const void* p) {
    uint32_t a;
    asm("{ .reg .u64 t; cvta.to.shared.u64 t, %1; cvt.u32.u64 %0, t; }"
        : "=r"(a) : "l"(p));
    return a;
}
__device__ __forceinline__ uint32_t prmt(uint32_t a, uint32_t b, uint32_t s) {
    uint32_t r;
    asm("prmt.b32 %0, %1, %2, %3;" : "=r"(r) : "r"(a), "r"(b), "r"(s));
    return r;
}
__device__ __forceinline__ void ldm4(uint32_t* r, uint32_t addr) {
    asm volatile("ldmatrix.sync.aligned.m8n8.x4.shared.b16 {%0,%1,%2,%3}, [%4];"
                 : "=r"(r[0]), "=r"(r[1]), "=r"(r[2]), "=r"(r[3]) : "r"(addr));
}
__device__ __forceinline__ void mma16816h(float* d, const uint32_t* a,
                                          uint32_t b0, uint32_t b1) {
    asm volatile(
        "mma.sync.aligned.m16n8k16.row.col.f32.f16.f16.f32 "
        "{%0,%1,%2,%3}, {%4,%5,%6,%7}, {%8,%9}, {%0,%1,%2,%3};"
        : "+f"(d[0]), "+f"(d[1]), "+f"(d[2]), "+f"(d[3])
        : "r"(a[0]), "r"(a[1]), "r"(a[2]), "r"(a[3]), "r"(b0), "r"(b1));
}
__device__ __forceinline__ uint2 cvt4h(const float4 v) {
    __half2 p0 = __floats2half2_rn(v.x, v.y);
    __half2 p1 = __floats2half2_rn(v.z, v.w);
    uint2 r;
    r.x = *reinterpret_cast<const uint32_t*>(&p0);
    r.y = *reinterpret_cast<const uint32_t*>(&p1);
    return r;
}

// ---------------------------------------------------------------------------
// Kernel 0: one-shot conversions + epoch bump. A -> fp16; W_ih -> fp16.
// ---------------------------------------------------------------------------
__global__ void __launch_bounds__(256) conv_kernel(
    const float* __restrict__ A, const float* __restrict__ W)
{
    if (blockIdx.x == 0 && threadIdx.x == 0) g_epoch = g_epoch + 1u;
    size_t i = (size_t)blockIdx.x * 256 + threadIdx.x;
    size_t base = i * 8;
    if (base < (size_t)MTOT * IDIM) {
        float4 v0 = *(const float4*)(A + base);
        float4 v1 = *(const float4*)(A + base + 4);
        uint2 a = cvt4h(v0), b = cvt4h(v1);
        *(uint4*)(g_Ah16 + base) = make_uint4(a.x, a.y, b.x, b.y);
    }
    if (base < (size_t)G4 * IDIM) {
        float4 w0 = *(const float4*)(W + base);
        float4 w1 = *(const float4*)(W + base + 4);
        uint2 h0 = cvt4h(w0), h1 = cvt4h(w1);
        *(uint4*)(g_Wh16 + base) = make_uint4(h0.x, h0.y, h1.x, h1.y);
    }
}

// ---------------------------------------------------------------------------
// Kernel 1: fused recurrence + input projection.
// Grid (32 col-groups, 4 batch-groups). 16 warps = kw(8 K-slices) x nw(2).
// Per step per warp: 16 xp-MMAs (A(t)*W_ih, off-chain in poll bubble) +
// 16 h-MMAs (h(t+1)*W_hh, on-chain). Tagged-word h exchange (1 L2 RT).
// W_hh frags in regs; W_ih plane resident in SMEM (ldm per step).
// ---------------------------------------------------------------------------
#define OFF_WIH  0                 // 64 rows x 1040 B, persists
#define OFF_WHH  66560             // init staging, reused by p9 after
#define OFF_P9A  66560             // float [8][1092] = 34944 B
#define OFF_P9B  103424
#define OFF_HHI  138368            // h plane: 16 rows x 1040
#define OFF_A0   155008            // A plane parity 0: 16 rows x 1040
#define OFF_A1   171648            // A plane parity 1
#define R_SMEM   188544

// Poll a 16x64 h slice (tagged u32 words) until all tags == tt, then pack the
// fp16 payloads into the SMEM h plane. Two phases of 4 x uint4 per lane.
__device__ __forceinline__ void stage_slice(char* sm, int lane, int kw, int B0,
                                            const uint32_t* hb, uint32_t tt)
{
#pragma unroll
    for (int ph = 0; ph < 2; ph++) {
        uint4 pv[4];
        unsigned ok;
        do {
            ok = 1u;
#pragma unroll
            for (int j = 0; j < 4; j++) {
                int idx = (ph * 4 + j) * 32 + lane;
                int r = idx >> 4, c4 = (idx & 15) * 4;
                const uint32_t* p = hb + (size_t)(B0 + r) * HDIM + kw * 64 + c4;
                asm volatile("ld.relaxed.gpu.global.v4.u32 {%0,%1,%2,%3}, [%4];"
                             : "=r"(pv[j].x), "=r"(pv[j].y),
                               "=r"(pv[j].z), "=r"(pv[j].w)
                             : "l"(p));
                ok &= (unsigned)((pv[j].x >> 16) == tt);
                ok &= (unsigned)((pv[j].y >> 16) == tt);
                ok &= (unsigned)((pv[j].z >> 16) == tt);
                ok &= (unsigned)((pv[j].w >> 16) == tt);
            }
        } while (!__all_sync(0xffffffffu, ok));
#pragma unroll
        for (int j = 0; j < 4; j++) {
            int idx = (ph * 4 + j) * 32 + lane;
            int r = idx >> 4, c4 = (idx & 15) * 4;
            uint2 pk;
            pk.x = prmt(pv[j].x, pv[j].y, 0x5410);
            pk.y = prmt(pv[j].z, pv[j].w, 0x5410);
            *(uint2*)(sm + OFF_HHI + r * 1040 + (kw * 64 + c4) * 2) = pk;
        }
    }
}

// Stage the static A(t2) slice (16 batches x 64 fp16) into parity plane.
__device__ __forceinline__ void stage_A(char* sm, int lane, int kw, int B0,
                                        int t2, uint32_t offA)
{
#pragma unroll
    for (int j = 0; j < 4; j++) {
        int idx = j * 32 + lane;
        int r = idx >> 3, c8 = (idx & 7) * 8;
        uint4 v = *(const uint4*)(g_Ah16
                    + ((size_t)t2 * BATCH + B0 + r) * IDIM + kw * 64 + c8);
        *(uint4*)(sm + offA + r * 1040 + (kw * 64 + c8) * 2) = v;
    }
}

__global__ void __launch_bounds__(512, 1) recur_mma_kernel(
    const float* __restrict__ h0, const float* __restrict__ c0,
    const float* __restrict__ Whh,
    const float* __restrict__ bih, const float* __restrict__ bhh,
    float* __restrict__ out)
{
    extern __shared__ char sm[];

    const int tid  = threadIdx.x;
    const int lane = tid & 31, wid = tid >> 5;
    const int kw = wid >> 1;
    const int nw = wid & 1;
    const int cg = blockIdx.x;
    const int j0 = cg * 16;
    const int B0 = blockIdx.y * 16;
    const uint32_t tagb = (g_epoch & 31u) << 11;   // 5-bit epoch | 11-bit t

    // ---- load W_ih plane (persist) + W_hh staging plane ----
#pragma unroll 4
    for (int i = 0; i < 8; i++) {          // W_ih: 4096 uint4
        int idx = tid + i * 512;
        int row = idx >> 6;                // 0..63 (gate*16+jj)
        int c16 = (idx & 63) * 8;
        int gate = row >> 4, jj = row & 15;
        uint4 v = *(const uint4*)(g_Wh16
                    + (size_t)(gate * HDIM + j0 + jj) * IDIM + c16);
        *(uint4*)(sm + OFF_WIH + row * 1040 + c16 * 2) = v;
    }
#pragma unroll 4
    for (int i = 0; i < 16; i++) {         // W_hh fp32 -> fp16 staging
        int idx = tid + i * 512;
        int row = idx >> 7;
        int f4  = (idx & 127) << 2;
        int gate = row >> 4, jj = row & 15;
        float4 v = *(const float4*)(Whh
                      + (size_t)(gate * HDIM + j0 + jj) * HDIM + f4);
        *(uint2*)(sm + OFF_WHH + row * 1040 + f4 * 2) = cvt4h(v);
    }
    __syncthreads();

    // ---- W_hh fragments -> registers ----
    const int lr = lane & 7, sel = lane >> 3;
    uint32_t BH[4][2][4];
#pragma unroll
    for (int ks = 0; ks < 4; ks++)
#pragma unroll
        for (int p = 0; p < 2; p++) {
            uint32_t off = (uint32_t)(nw * 32 + p * 16 + (sel & 1) * 8 + lr) * 1040u
                         + (uint32_t)((sel >> 1) * 16)
                         + (uint32_t)(kw * 128 + ks * 32);
            ldm4(BH[ks][p], smem_u32(sm + OFF_WHH) + off);
        }

    // fragment row offset shared by h and A planes
    const uint32_t aRowOff = (uint32_t)((sel & 1) * 8 + lr) * 1040u
                           + (uint32_t)((sel >> 1) * 16)
                           + (uint32_t)(kw * 128);
    const uint32_t aHiB  = smem_u32(sm + OFF_HHI) + aRowOff;
    const uint32_t axB0  = smem_u32(sm + OFF_A0)  + aRowOff;
    const uint32_t axB1  = smem_u32(sm + OFF_A1)  + aRowOff;
    // W_ih fragment base (per-step ldm)
    const uint32_t wihB  = smem_u32(sm + OFF_WIH)
                         + (uint32_t)(nw * 32 + (sel & 1) * 8 + lr) * 1040u
                         + (uint32_t)((sel >> 1) * 16)
                         + (uint32_t)(kw * 128);

    float creg = 0.0f, bs0 = 0.f, bs1 = 0.f, bs2 = 0.f, bs3 = 0.f;
    int cb_ = 0, cjj_ = 0;

    if (nw == 0) {
        int ct = kw * 32 + lane;
        cb_ = ct >> 4; cjj_ = ct & 15;
        creg = c0[(size_t)(B0 + cb_) * HDIM + j0 + cjj_];
        bs0 = bih[0 * HDIM + j0 + cjj_] + bhh[0 * HDIM + j0 + cjj_];
        bs1 = bih[1 * HDIM + j0 + cjj_] + bhh[1 * HDIM + j0 + cjj_];
        bs2 = bih[2 * HDIM + j0 + cjj_] + bhh[2 * HDIM + j0 + cjj_];
        bs3 = bih[3 * HDIM + j0 + cjj_] + bhh[3 * HDIM + j0 + cjj_];
        float hv = h0[(size_t)(B0 + cb_) * HDIM + j0 + cjj_];
        uint32_t hw = ((tagb | 1024u) << 16)
                    | (uint32_t)__half_as_ushort(__float2half_rn(hv));
        uint32_t* hp = g_h32 + (size_t)(B0 + cb_) * HDIM + j0 + cjj_; // buf 0
        asm volatile("st.relaxed.gpu.global.u32 [%0], %1;"
                     :: "l"(hp), "r"(hw) : "memory");
    } else {
        stage_A(sm, lane, kw, B0, T_STEPS - 1, OFF_A1);   // A(1023) parity 1
        stage_A(sm, lane, kw, B0, T_STEPS - 2, OFF_A0);   // A(1022) parity 0
        stage_slice(sm, lane, kw, B0, g_h32, tagb | 1024u);  // h0, buf 0
    }
    __syncthreads();   // W_hh staging free for p9; planes visible to all

    // ---- xp MMA for t=1023 (A parity 1) ----
    float acc[4][4];
#pragma unroll
    for (int q = 0; q < 4; q++)
#pragma unroll
        for (int i = 0; i < 4; i++) acc[q][i] = 0.0f;
#pragma unroll
    for (int ks = 0; ks < 4; ks++) {
        uint32_t ax[4], w0[4], w1[4];
        ldm4(ax, axB1 + (uint32_t)(ks * 32));
        ldm4(w0, wihB + (uint32_t)(ks * 32));
        ldm4(w1, wihB + 16 * 1040u + (uint32_t)(ks * 32));
        mma16816h(acc[0], ax, w0[0], w0[2]);
        mma16816h(acc[1], ax, w0[1], w0[3]);
        mma16816h(acc[2], ax, w1[0], w1[2]);
        mma16816h(acc[3], ax, w1[1], w1[3]);
    }

    for (int t = T_STEPS - 1; t >= 0; t--) {
        asm volatile("bar.sync %0, 64;" :: "r"(1 + kw) : "memory");

        // ---- h MMA (on-chain): 4 k16 steps ----
        uint32_t ah[4][4];
#pragma unroll
        for (int ks = 0; ks < 4; ks++)
            ldm4(ah[ks], aHiB + (uint32_t)(ks * 32));
#pragma unroll
        for (int ks = 0; ks < 4; ks++) {
#pragma unroll
            for (int q = 0; q < 4; q++) {
                const int p = q >> 1, hh = q & 1;
                mma16816h(acc[q], ah[ks], BH[ks][p][hh], BH[ks][p][hh + 2]);
            }
        }
        float* p9 = (float*)(sm + ((t & 1) ? OFF_P9B : OFF_P9A));
        {
            const int r = lane >> 2;
            const int c2 = (lane & 3) * 2;
            float* base = p9 + kw * 1092;
#pragma unroll
            for (int q = 0; q < 4; q++) {
                int cc = nw * 32 + q * 8 + c2;
                *(float2*)(base + r * 68 + cc)       = make_float2(acc[q][0], acc[q][1]);
                *(float2*)(base + (r + 8) * 68 + cc) = make_float2(acc[q][2], acc[q][3]);
            }
        }

        if (nw == 0) {
            asm volatile("bar.sync 9, 512;" ::: "memory");
            float pre[4];
#pragma unroll
            for (int g = 0; g < 4; g++) {
                int off = cb_ * 68 + g * 16 + cjj_;
                float s0 = p9[off]            + p9[1092 + off];
                float s1 = p9[2 * 1092 + off] + p9[3 * 1092 + off];
                float s2 = p9[4 * 1092 + off] + p9[5 * 1092 + off];
                float s3 = p9[6 * 1092 + off] + p9[7 * 1092 + off];
                pre[g] = (s0 + s1) + (s2 + s3);
            }
            float gi = sigf(pre[0] + bs0);
            float gf = sigf(pre[1] + bs1);
            float gz = sigf(pre[2] + bs2);
            float go = sigf(pre[3] + bs3);
            float cn = gf * creg + gz - gi;
            creg = cn;
            float hn = sigf(cn) - go;
            // publish tagged h word first (single L2 RT hand-off)
            uint32_t hw = ((tagb | (uint32_t)t) << 16)
                        | (uint32_t)__half_as_ushort(__float2half_rn(hn));
            uint32_t* hp = g_h32 + (size_t)(t & 1) * BHD
                         + (size_t)(B0 + cb_) * HDIM + j0 + cjj_;
            asm volatile("st.relaxed.gpu.global.u32 [%0], %1;"
                         :: "l"(hp), "r"(hw) : "memory");
            out[(size_t)t * BHD + (size_t)(B0 + cb_) * HDIM + j0 + cjj_] = hn;
            if (t == 0) {
                const size_t base = (size_t)T_STEPS * BHD;
                out[base + (size_t)(B0 + cb_) * HDIM + j0 + cjj_] = hn;
                out[base + BHD + (size_t)(B0 + cb_) * HDIM + j0 + cjj_] = cn;
            }
            // ---- xp MMA(t-1) while stage warp polls (off-chain) ----
            if (t > 0) {
                const uint32_t axB = ((t - 1) & 1) ? axB1 : axB0;
#pragma unroll
                for (int q = 0; q < 4; q++)
#pragma unroll
                    for (int i = 0; i < 4; i++) acc[q][i] = 0.0f;
#pragma unroll
                for (int ks = 0; ks < 4; ks++) {
                    uint32_t ax[4], w0[4], w1[4];
                    ldm4(ax, axB + (uint32_t)(ks * 32));
                    ldm4(w0, wihB + (uint32_t)(ks * 32));
                    ldm4(w1, wihB + 16 * 1040u + (uint32_t)(ks * 32));
                    mma16816h(acc[0], ax, w0[0], w0[2]);
                    mma16816h(acc[1], ax, w0[1], w0[3]);
                    mma16816h(acc[2], ax, w1[0], w1[2]);
                    mma16816h(acc[3], ax, w1[1], w1[3]);
                }
            }
        } else {
            asm volatile("bar.arrive 9, 512;" ::: "memory");
            if (t > 0) {
                if (t >= 2)
                    stage_A(sm, lane, kw, B0, t - 2,
                            ((t - 2) & 1) ? OFF_A1 : OFF_A0);
                // ---- xp MMA(t-1) before the poll (off-chain) ----
                const uint32_t axB = ((t - 1) & 1) ? axB1 : axB0;
#pragma unroll
                for (int q = 0; q < 4; q++)
#pragma unroll
                    for (int i = 0; i < 4; i++) acc[q][i] = 0.0f;
#pragma unroll
                for (int ks = 0; ks < 4; ks++) {
                    uint32_t ax[4], w0[4], w1[4];
                    ldm4(ax, axB + (uint32_t)(ks * 32));
                    ldm4(w0, wihB + (uint32_t)(ks * 32));
                    ldm4(w1, wihB + 16 * 1040u + (uint32_t)(ks * 32));
                    mma16816h(acc[0], ax, w0[0], w0[2]);
                    mma16816h(acc[1], ax, w0[1], w0[3]);
                    mma16816h(acc[2], ax, w1[0], w1[2]);
                    mma16816h(acc[3], ax, w1[1], w1[3]);
                }
                // poll + stage h(t) (tag t, buffer t&1)
                stage_slice(sm, lane, kw, B0,
                            g_h32 + (size_t)(t & 1) * BHD,
                            tagb | (uint32_t)t);
            }
        }
    }
}

// ---------------------------------------------------------------------------
extern "C" void kernel_launch(void* const* d_in, const int* in_sizes, int n_in,
                              void* d_out, int out_size)
{
    const float* input = (const float*)d_in[0];
    const float* h0    = (const float*)d_in[1];
    const float* c0    = (const float*)d_in[2];
    const float* Wih   = (const float*)d_in[3];
    const float* Whh   = (const float*)d_in[4];
    const float* bih   = (const float*)d_in[5];
    const float* bhh   = (const float*)d_in[6];
    float* out = (float*)d_out;

    static int configured = 0;
    if (!configured) {
        cudaFuncSetAttribute(recur_mma_kernel,
                             cudaFuncAttributeMaxDynamicSharedMemorySize,
                             R_SMEM);
        configured = 1;
    }

    conv_kernel<<<(int)(((size_t)MTOT * IDIM / 8 + 255) / 256), 256>>>(input, Wih);
    recur_mma_kernel<<<dim3(HDIM / 16, BATCH / 16), 512, R_SMEM>>>(
        h0, c0, Whh, bih, bhh, out);
}